// round 11
// baseline (speedup 1.0000x reference)
#include <cuda_runtime.h>
#include <cuda_fp16.h>
#include <math.h>

#define N_NODES 1048576
#define N_EDGES 4194304
#define EPSV 1e-5f
#define STATS_LEN (7*24 + 3*12)

// ---------------- scratch (static device globals; zero-init at load) ----------------
__device__ float  g_hA[N_NODES * 12];
__device__ float  g_hB[N_NODES * 12];
__device__ __half g_hHA[N_NODES * 16];   // fp16 mirror (32B rows) for gather
__device__ __half g_hHB[N_NODES * 16];
__device__ float4 g_xp[N_NODES];         // x packed to float4
__device__ int    g_deg[N_NODES];        // zeroed by k_scanA for next call
__device__ int    g_off[N_NODES + 1];
__device__ int    g_cur[N_NODES];
__device__ int    g_bsum[1024];
__device__ int    g_srt[N_EDGES];        // src ids grouped by dst (CSR adjacency)
__device__ float  g_stats[STATS_LEN];    // zeroed by k_scanB for next call

__device__ __forceinline__ float*  bufptr(int s)  { return s == 0 ? g_hA : g_hB; }
__device__ __forceinline__ __half* bufptrH(int s) { return s == 0 ? g_hHA : g_hHB; }

__device__ __forceinline__ void warpsum(float& v) {
#pragma unroll
    for (int o = 16; o; o >>= 1) v += __shfl_xor_sync(0xffffffffu, v, o);
}

// fp16 gather: 24 useful bytes in 2 loads (row is 32B aligned, single 128B line).
__device__ __forceinline__ void gathH(float* acc, const __half* hH, int s) {
    const __half* r = hH + ((size_t)s << 4);
    uint4 a = __ldg(reinterpret_cast<const uint4*>(r));
    uint2 b = __ldg(reinterpret_cast<const uint2*>(r + 8));
    float2 f;
    f = __half22float2(*reinterpret_cast<__half2*>(&a.x)); acc[0] += f.x; acc[1] += f.y;
    f = __half22float2(*reinterpret_cast<__half2*>(&a.y)); acc[2] += f.x; acc[3] += f.y;
    f = __half22float2(*reinterpret_cast<__half2*>(&a.z)); acc[4] += f.x; acc[5] += f.y;
    f = __half22float2(*reinterpret_cast<__half2*>(&a.w)); acc[6] += f.x; acc[7] += f.y;
    f = __half22float2(*reinterpret_cast<__half2*>(&b.x)); acc[8] += f.x; acc[9] += f.y;
    f = __half22float2(*reinterpret_cast<__half2*>(&b.y)); acc[10] += f.x; acc[11] += f.y;
}

__device__ __forceinline__ void storeH(__half* hH, int i, const float* out) {
    __half* r = hH + ((size_t)i << 4);
    uint4 a; uint2 b;
    *reinterpret_cast<__half2*>(&a.x) = __floats2half2_rn(out[0], out[1]);
    *reinterpret_cast<__half2*>(&a.y) = __floats2half2_rn(out[2], out[3]);
    *reinterpret_cast<__half2*>(&a.z) = __floats2half2_rn(out[4], out[5]);
    *reinterpret_cast<__half2*>(&a.w) = __floats2half2_rn(out[6], out[7]);
    *reinterpret_cast<__half2*>(&b.x) = __floats2half2_rn(out[8], out[9]);
    *reinterpret_cast<__half2*>(&b.y) = __floats2half2_rn(out[10], out[11]);
    *reinterpret_cast<uint4*>(r) = a;
    *reinterpret_cast<uint2*>(r + 8) = b;
}

// ---------------- CSR build ----------------

// degree histogram (2 edges/thread, int2 loads) + x packing (float4 loads, 4 nodes/thread)
__global__ void k_degx(const int* __restrict__ ei, const float4* __restrict__ x4) {
    int t = blockIdx.x * blockDim.x + threadIdx.x;   // 0 .. N_EDGES/2-1
    int2 d = __ldcs(reinterpret_cast<const int2*>(ei + N_EDGES) + t);
    atomicAdd(&g_deg[d.x], 1);
    atomicAdd(&g_deg[d.y], 1);
    if (t < N_NODES / 4) {
        float4 a = __ldcs(x4 + 3 * t);
        float4 b = __ldcs(x4 + 3 * t + 1);
        float4 c = __ldcs(x4 + 3 * t + 2);
        g_xp[4 * t + 0] = make_float4(a.x, a.y, a.z, 0.f);
        g_xp[4 * t + 1] = make_float4(a.w, b.x, b.y, 0.f);
        g_xp[4 * t + 2] = make_float4(b.z, b.w, c.x, 0.f);
        g_xp[4 * t + 3] = make_float4(c.y, c.z, c.w, 0.f);
    }
}

// local exclusive scan: 1024 blocks x 1024 elements (256 thr x 4); re-zeroes g_deg
__global__ void k_scanA() {
    __shared__ int sh[256];
    int t = threadIdx.x;
    int base = blockIdx.x * 1024 + t * 4;
    int4 d = *reinterpret_cast<int4*>(&g_deg[base]);
    *reinterpret_cast<int4*>(&g_deg[base]) = make_int4(0, 0, 0, 0);
    int s1 = d.x + d.y, s2 = s1 + d.z, tot = s2 + d.w;
    sh[t] = tot;
    __syncthreads();
#pragma unroll
    for (int o = 1; o < 256; o <<= 1) {
        int v = (t >= o) ? sh[t - o] : 0;
        __syncthreads();
        sh[t] += v;
        __syncthreads();
    }
    int excl = sh[t] - tot;
    g_off[base + 0] = excl;
    g_off[base + 1] = excl + d.x;
    g_off[base + 2] = excl + s1;
    g_off[base + 3] = excl + s2;
    if (t == 255) g_bsum[blockIdx.x] = sh[255];
}

// finalize offsets; block 0 re-zeroes g_stats
__global__ void k_scanB() {
    __shared__ int sred[9];
    int t = threadIdx.x;
    if (blockIdx.x == 0 && t < STATS_LEN) g_stats[t] = 0.f;
    int q = blockIdx.x >> 2;
    int4 v = *reinterpret_cast<int4*>(&g_bsum[t * 4]);
    int j0 = t * 4;
    int s = (j0 + 0 < q ? v.x : 0) + (j0 + 1 < q ? v.y : 0)
          + (j0 + 2 < q ? v.z : 0) + (j0 + 3 < q ? v.w : 0);
#pragma unroll
    for (int o = 16; o; o >>= 1) s += __shfl_xor_sync(0xffffffffu, s, o);
    if ((t & 31) == 0) sred[t >> 5] = s;
    __syncthreads();
    if (t == 0) {
        int r0 = 0;
#pragma unroll
        for (int w = 0; w < 8; w++) r0 += sred[w];
        sred[8] = r0;
    }
    __syncthreads();
    int S = sred[8];
    int i = blockIdx.x * 256 + t;
    int val = g_off[i] + S;
    g_off[i] = val;
    g_cur[i] = val;
    if (i == 0) g_off[N_NODES] = N_EDGES;
}

// edge placement: 2 edges/thread, int2 loads, two independent atomic/store chains
__global__ void k_place(const int* __restrict__ ei) {
    int t = blockIdx.x * blockDim.x + threadIdx.x;   // 0 .. N_EDGES/2-1
    int2 s = __ldcs(reinterpret_cast<const int2*>(ei) + t);
    int2 d = __ldcs(reinterpret_cast<const int2*>(ei + N_EDGES) + t);
    int p0 = atomicAdd(&g_cur[d.x], 1);
    int p1 = atomicAdd(&g_cur[d.y], 1);
    g_srt[p0] = s.x;
    g_srt[p1] = s.y;
}

// ---------------- layer 1: float4-packed x gather (1 LDG/neighbor) ----------------
__global__ void k_node1f(const float* __restrict__ Wl1, const float* __restrict__ Wr1,
                         const float* __restrict__ b1) {
    __shared__ float sWl[36], sWr[36], sb[12], sSum[24];
    int t = threadIdx.x;
    if (t < 36) { sWl[t] = Wl1[t]; sWr[t] = Wr1[t]; }
    if (t < 12) sb[t] = b1[t];
    if (t < 24) sSum[t] = 0.f;
    __syncthreads();
    int i = blockIdx.x * blockDim.x + t;
    int beg = g_off[i], end = g_off[i + 1];
    float a0 = 0.f, a1 = 0.f, a2 = 0.f;
    int p = beg;
    for (; p + 2 <= end; p += 2) {
        int s0 = __ldg(&g_srt[p]), s1 = __ldg(&g_srt[p + 1]);
        float4 u = __ldg(&g_xp[s0]);
        float4 w = __ldg(&g_xp[s1]);
        a0 += u.x + w.x; a1 += u.y + w.y; a2 += u.z + w.z;
    }
    if (p < end) {
        float4 u = __ldg(&g_xp[__ldg(&g_srt[p])]);
        a0 += u.x; a1 += u.y; a2 += u.z;
    }
    int dg = end - beg;
    float inv = dg > 0 ? 1.f / (float)dg : 0.f;
    float m0 = a0 * inv, m1 = a1 * inv, m2 = a2 * inv;
    float4 xs = __ldg(&g_xp[i]);
    float out[12];
#pragma unroll
    for (int k = 0; k < 12; k++) {
        float v = sb[k] + m0 * sWl[3 * k] + m1 * sWl[3 * k + 1] + m2 * sWl[3 * k + 2]
                        + xs.x * sWr[3 * k] + xs.y * sWr[3 * k + 1] + xs.z * sWr[3 * k + 2];
        out[k] = fmaxf(v, 0.f);
    }
    float4* hp = reinterpret_cast<float4*>(g_hA + (size_t)i * 12);
    __stcs(hp + 0, make_float4(out[0], out[1], out[2], out[3]));
    __stcs(hp + 1, make_float4(out[4], out[5], out[6], out[7]));
    __stcs(hp + 2, make_float4(out[8], out[9], out[10], out[11]));
    storeH(g_hHA, i, out);
#pragma unroll
    for (int k = 0; k < 12; k++) {
        float s = out[k], q = out[k] * out[k];
        warpsum(s); warpsum(q);
        if ((t & 31) == 0) { atomicAdd(&sSum[k], s); atomicAdd(&sSum[12 + k], q); }
    }
    __syncthreads();
    if (t < 24) atomicAdd(&g_stats[t], sSum[t]);
}

// ---------------- layers 2..8: fp16 gather (2 LDG/neighbor), fp32 everywhere else ----
template <int MODE>
__global__ void k_nodef(int in_sel, int out_sel,
                        const float* __restrict__ Wl, const float* __restrict__ Wr,
                        const float* __restrict__ bias,
                        const float* __restrict__ bng, const float* __restrict__ bnb,
                        int sin_off, int sout_off,
                        const float* __restrict__ linW, const float* __restrict__ linb) {
    const float*  h_in  = bufptr(in_sel);
    const __half* hH_in = bufptrH(in_sel);
    float*  h_out  = bufptr(out_sel);
    __half* hH_out = bufptrH(out_sel);
    __shared__ float sWl[144], sWr[144], sb[12], sa[12], sc[12], sSum[24], sLW[36], sLB[6];
    int t = threadIdx.x;
    if (t < 144) { sWl[t] = Wl[t]; sWr[t] = Wr[t]; }
    if (t < 12) {
        sb[t] = bias[t];
        float mean = g_stats[sin_off + t] * (1.f / N_NODES);
        float var  = g_stats[sin_off + 12 + t] * (1.f / N_NODES) - mean * mean;
        float a = bng[t] * rsqrtf(var + EPSV);
        sa[t] = a;
        sc[t] = bnb[t] - mean * a;
    }
    if (t < 24) sSum[t] = 0.f;
    if (MODE == 1) {
        if (t < 36) sLW[t] = linW[t];
        if (t < 6)  sLB[t] = linb[t];
    }
    __syncthreads();
    int i = blockIdx.x * blockDim.x + t;
    int beg = g_off[i], end = g_off[i + 1];
    float acc[12];
#pragma unroll
    for (int j = 0; j < 12; j++) acc[j] = 0.f;
    int p = beg;
    for (; p + 2 <= end; p += 2) {
        int s0 = __ldg(&g_srt[p]), s1 = __ldg(&g_srt[p + 1]);
        gathH(acc, hH_in, s0);
        gathH(acc, hH_in, s1);
    }
    if (p < end) gathH(acc, hH_in, __ldg(&g_srt[p]));

    const float4* hp = reinterpret_cast<const float4*>(h_in + (size_t)i * 12);
    float4 h0 = __ldcs(hp + 0), h1 = __ldcs(hp + 1), h2 = __ldcs(hp + 2);
    float hv[12] = {h0.x, h0.y, h0.z, h0.w, h1.x, h1.y, h1.z, h1.w, h2.x, h2.y, h2.z, h2.w};
    int dg = end - beg;
    float gate = dg > 0 ? 1.f : 0.f;
    float inv  = dg > 0 ? 1.f / (float)dg : 0.f;
    float m[12], hb[12];
#pragma unroll
    for (int j = 0; j < 12; j++) {
        m[j]  = acc[j] * inv * sa[j] + sc[j] * gate;   // bn(mean) fold; isolated -> 0
        hb[j] = hv[j] * sa[j] + sc[j];
    }
    float out[12];
#pragma unroll
    for (int k = 0; k < 12; k++) {
        float v = sb[k];
#pragma unroll
        for (int j = 0; j < 12; j++) v += m[j] * sWl[12 * k + j] + hb[j] * sWr[12 * k + j];
        out[k] = fmaxf(v, 0.f);
    }
    float4* op = reinterpret_cast<float4*>(h_out + (size_t)i * 12);
    __stcs(op + 0, make_float4(out[0], out[1], out[2], out[3]));
    __stcs(op + 1, make_float4(out[4], out[5], out[6], out[7]));
    __stcs(op + 2, make_float4(out[8], out[9], out[10], out[11]));
    storeH(hH_out, i, out);
    if (MODE == 0) {
#pragma unroll
        for (int k = 0; k < 12; k++) {
            float s = out[k], q = out[k] * out[k];
            warpsum(s); warpsum(q);
            if ((t & 31) == 0) { atomicAdd(&sSum[k], s); atomicAdd(&sSum[12 + k], q); }
        }
        __syncthreads();
        if (t < 24) atomicAdd(&g_stats[sout_off + t], sSum[t]);
    } else {
#pragma unroll
        for (int k = 0; k < 6; k++) {
            float za = sLB[k], zb = sLB[k];
#pragma unroll
            for (int j = 0; j < 6; j++) { za += out[j] * sLW[6 * k + j]; zb += out[6 + j] * sLW[6 * k + j]; }
            float s = za + zb, q = za * za + zb * zb;
            warpsum(s); warpsum(q);
            if ((t & 31) == 0) { atomicAdd(&sSum[k], s); atomicAdd(&sSum[6 + k], q); }
        }
        __syncthreads();
        if (t < 12) atomicAdd(&g_stats[sout_off + t], sSum[t]);
    }
}

// ---------------- head (all fp32, streaming) ----------------
template <int PASS>
__global__ void k_head(int in_sel, int out_sel,
                       const float* __restrict__ linW, const float* __restrict__ linb,
                       const float* __restrict__ g6, const float* __restrict__ b6,
                       int sin_off, int sout_off,
                       const float* __restrict__ oW, const float* __restrict__ ob,
                       float* __restrict__ outp) {
    const float* h_in = bufptr(in_sel);
    float* h_out = bufptr(out_sel);
    __shared__ float sLW[36], sLB[6], sa[6], sc[6], sSum[12], sOW[7];
    int t = threadIdx.x;
    if (t < 36) sLW[t] = linW[t];
    if (t < 6) {
        sLB[t] = linb[t];
        const float invM = 1.f / (2.f * N_NODES);
        float mean = g_stats[sin_off + t] * invM;
        float var  = g_stats[sin_off + 6 + t] * invM - mean * mean;
        float a = g6[t] * rsqrtf(var + EPSV);
        sa[t] = a;
        sc[t] = b6[t] - mean * a;
    }
    if (t < 12) sSum[t] = 0.f;
    if (PASS == 3) { if (t < 6) sOW[t] = oW[t]; if (t == 6) sOW[6] = ob[0]; }
    __syncthreads();
    int i = blockIdx.x * blockDim.x + t;
    const float4* hp = reinterpret_cast<const float4*>(h_in + (size_t)i * 12);
    float4 h0 = __ldcs(hp + 0), h1 = __ldcs(hp + 1), h2 = __ldcs(hp + 2);
    float hv[12] = {h0.x, h0.y, h0.z, h0.w, h1.x, h1.y, h1.z, h1.w, h2.x, h2.y, h2.z, h2.w};
    float r[12];
#pragma unroll
    for (int half = 0; half < 2; half++) {
#pragma unroll
        for (int k = 0; k < 6; k++) {
            float z = sLB[k];
#pragma unroll
            for (int j = 0; j < 6; j++) z += hv[6 * half + j] * sLW[6 * k + j];
            r[6 * half + k] = fmaxf(z * sa[k] + sc[k], 0.f);
        }
    }
    if (PASS < 3) {
        float4* op = reinterpret_cast<float4*>(h_out + (size_t)i * 12);
        __stcs(op + 0, make_float4(r[0], r[1], r[2], r[3]));
        __stcs(op + 1, make_float4(r[4], r[5], r[6], r[7]));
        __stcs(op + 2, make_float4(r[8], r[9], r[10], r[11]));
#pragma unroll
        for (int k = 0; k < 6; k++) {
            float za = sLB[k], zb = sLB[k];
#pragma unroll
            for (int j = 0; j < 6; j++) { za += r[j] * sLW[6 * k + j]; zb += r[6 + j] * sLW[6 * k + j]; }
            float s = za + zb, q = za * za + zb * zb;
            warpsum(s); warpsum(q);
            if ((t & 31) == 0) { atomicAdd(&sSum[k], s); atomicAdd(&sSum[6 + k], q); }
        }
        __syncthreads();
        if (t < 12) atomicAdd(&g_stats[sout_off + t], sSum[t]);
    } else {
        float oa = sOW[6], obv = sOW[6];
#pragma unroll
        for (int j = 0; j < 6; j++) { oa += r[j] * sOW[j]; obv += r[6 + j] * sOW[j]; }
        outp[2 * i]     = 1.f / (1.f + expf(-oa));
        outp[2 * i + 1] = 1.f / (1.f + expf(-obv));
    }
}

// ---------------- launch ----------------
extern "C" void kernel_launch(void* const* d_in, const int* in_sizes, int n_in,
                              void* d_out, int out_size) {
    const float* x    = (const float*)d_in[0];
    const int*   ei   = (const int*)d_in[1];
    const float* Wl1  = (const float*)d_in[2];
    const float* Wr1  = (const float*)d_in[3];
    const float* b1   = (const float*)d_in[4];
    const float* Wl   = (const float*)d_in[5];
    const float* Wr   = (const float*)d_in[6];
    const float* bb   = (const float*)d_in[7];
    const float* bng  = (const float*)d_in[8];
    const float* bnb  = (const float*)d_in[9];
    const float* linW = (const float*)d_in[10];
    const float* linb = (const float*)d_in[11];
    const float* g6   = (const float*)d_in[12];
    const float* b6   = (const float*)d_in[13];
    const float* oW   = (const float*)d_in[14];
    const float* ob   = (const float*)d_in[15];
    float* outp = (float*)d_out;

    const int E2B = N_EDGES / 2 / 256;   // 8192 (2 edges per thread)
    const int NB  = N_NODES / 256;       // 4096

    // CSR build (g_deg/g_stats zero at entry: load-time init or fused re-zeroing)
    k_degx<<<E2B, 256>>>(ei, (const float4*)x);
    k_scanA<<<1024, 256>>>();       // also re-zeroes g_deg for next call
    k_scanB<<<NB, 256>>>();         // block 0 also re-zeroes g_stats
    k_place<<<E2B, 256>>>(ei);

    // conv1 -> hA + fp16 mirror, stats slot 0
    k_node1f<<<NB, 256>>>(Wl1, Wr1, b1);

    int in_sel = 0, out_sel = 1;
    for (int i = 0; i < 7; i++) {
        int sin_off = 24 * i;
        if (i < 6) {
            k_nodef<0><<<NB, 256>>>(in_sel, out_sel, Wl + 144 * i, Wr + 144 * i, bb + 12 * i,
                                    bng + 12 * i, bnb + 12 * i, sin_off, 24 * (i + 1),
                                    linW, linb);
        } else {
            k_nodef<1><<<NB, 256>>>(in_sel, out_sel, Wl + 144 * i, Wr + 144 * i, bb + 12 * i,
                                    bng + 12 * i, bnb + 12 * i, sin_off, 7 * 24,
                                    linW, linb);
        }
        int tmp = in_sel; in_sel = out_sel; out_sel = tmp;
    }
    // conv8 output in hB (in_sel==1). Head: hB -> hA -> hB -> out.
    k_head<1><<<NB, 256>>>(1, 0, linW, linb, g6, b6, 168, 180, oW, ob, outp);
    k_head<2><<<NB, 256>>>(0, 1, linW, linb, g6, b6, 180, 192, oW, ob, outp);
    k_head<3><<<NB, 256>>>(1, 0, linW, linb, g6, b6, 192, 0, oW, ob, outp);
}

// round 12
// speedup vs baseline: 1.0510x; 1.0510x over previous
#include <cuda_runtime.h>
#include <cuda_fp16.h>
#include <math.h>

#define N_NODES 1048576
#define N_EDGES 4194304
#define EPSV 1e-5f
#define STATS_LEN (7*24 + 3*12)

// ---------------- scratch (static device globals; zero-init at load) ----------------
__device__ float  g_hA[N_NODES * 12];
__device__ float  g_hB[N_NODES * 12];
__device__ __half g_hHA[N_NODES * 16];   // fp16 mirror (32B rows) for gather
__device__ __half g_hHB[N_NODES * 16];
__device__ float4 g_xp[N_NODES];         // x packed to float4
__device__ int    g_deg[N_NODES];        // zeroed by k_scanA for next call
__device__ int    g_off[N_NODES + 1];
__device__ int    g_cur[N_NODES];
__device__ int    g_bsum[1024];
__device__ int    g_srt[N_EDGES];        // src ids grouped by dst (CSR adjacency)
__device__ float  g_stats[STATS_LEN];    // zeroed by k_scanB for next call

__device__ __forceinline__ float*  bufptr(int s)  { return s == 0 ? g_hA : g_hB; }
__device__ __forceinline__ __half* bufptrH(int s) { return s == 0 ? g_hHA : g_hHB; }

__device__ __forceinline__ void warpsum(float& v) {
#pragma unroll
    for (int o = 16; o; o >>= 1) v += __shfl_xor_sync(0xffffffffu, v, o);
}

// fp16 row gather via ONE 256-bit load (sm_100a+): the whole 32B row in a single
// L1tex wavefront. Words 6,7 are padding and discarded.
__device__ __forceinline__ void gathH(float* acc, const __half* hH, int s) {
    const __half* r = hH + ((size_t)s << 4);
    float v0, v1, v2, v3, v4, v5, v6, v7;
    asm volatile("ld.global.nc.v8.f32 {%0,%1,%2,%3,%4,%5,%6,%7}, [%8];"
                 : "=f"(v0), "=f"(v1), "=f"(v2), "=f"(v3),
                   "=f"(v4), "=f"(v5), "=f"(v6), "=f"(v7)
                 : "l"(r));
    unsigned u;
    float2 f;
    u = __float_as_uint(v0); f = __half22float2(*reinterpret_cast<__half2*>(&u)); acc[0] += f.x; acc[1] += f.y;
    u = __float_as_uint(v1); f = __half22float2(*reinterpret_cast<__half2*>(&u)); acc[2] += f.x; acc[3] += f.y;
    u = __float_as_uint(v2); f = __half22float2(*reinterpret_cast<__half2*>(&u)); acc[4] += f.x; acc[5] += f.y;
    u = __float_as_uint(v3); f = __half22float2(*reinterpret_cast<__half2*>(&u)); acc[6] += f.x; acc[7] += f.y;
    u = __float_as_uint(v4); f = __half22float2(*reinterpret_cast<__half2*>(&u)); acc[8] += f.x; acc[9] += f.y;
    u = __float_as_uint(v5); f = __half22float2(*reinterpret_cast<__half2*>(&u)); acc[10] += f.x; acc[11] += f.y;
    (void)v6; (void)v7;
}

__device__ __forceinline__ void storeH(__half* hH, int i, const float* out) {
    __half* r = hH + ((size_t)i << 4);
    uint4 a; uint2 b;
    *reinterpret_cast<__half2*>(&a.x) = __floats2half2_rn(out[0], out[1]);
    *reinterpret_cast<__half2*>(&a.y) = __floats2half2_rn(out[2], out[3]);
    *reinterpret_cast<__half2*>(&a.z) = __floats2half2_rn(out[4], out[5]);
    *reinterpret_cast<__half2*>(&a.w) = __floats2half2_rn(out[6], out[7]);
    *reinterpret_cast<__half2*>(&b.x) = __floats2half2_rn(out[8], out[9]);
    *reinterpret_cast<__half2*>(&b.y) = __floats2half2_rn(out[10], out[11]);
    *reinterpret_cast<uint4*>(r) = a;
    *reinterpret_cast<uint2*>(r + 8) = b;
}

// ---------------- CSR build ----------------

// degree histogram + x packing. ei is single-use here: streaming loads.
__global__ void k_degx(const int* __restrict__ ei, const float* __restrict__ x) {
    int e = blockIdx.x * blockDim.x + threadIdx.x;
    if (e < N_EDGES) atomicAdd(&g_deg[__ldcs(&ei[N_EDGES + e])], 1);
    if (e < N_NODES) {
        g_xp[e] = make_float4(__ldcs(&x[3 * e]), __ldcs(&x[3 * e + 1]),
                              __ldcs(&x[3 * e + 2]), 0.f);
    }
}

// local exclusive scan: 1024 blocks x 1024 elements (256 thr x 4); re-zeroes g_deg
__global__ void k_scanA() {
    __shared__ int sh[256];
    int t = threadIdx.x;
    int base = blockIdx.x * 1024 + t * 4;
    int4 d = *reinterpret_cast<int4*>(&g_deg[base]);
    *reinterpret_cast<int4*>(&g_deg[base]) = make_int4(0, 0, 0, 0);
    int s1 = d.x + d.y, s2 = s1 + d.z, tot = s2 + d.w;
    sh[t] = tot;
    __syncthreads();
#pragma unroll
    for (int o = 1; o < 256; o <<= 1) {
        int v = (t >= o) ? sh[t - o] : 0;
        __syncthreads();
        sh[t] += v;
        __syncthreads();
    }
    int excl = sh[t] - tot;
    g_off[base + 0] = excl;
    g_off[base + 1] = excl + d.x;
    g_off[base + 2] = excl + s1;
    g_off[base + 3] = excl + s2;
    if (t == 255) g_bsum[blockIdx.x] = sh[255];
}

// finalize offsets; block 0 re-zeroes g_stats
__global__ void k_scanB() {
    __shared__ int sred[9];
    int t = threadIdx.x;
    if (blockIdx.x == 0 && t < STATS_LEN) g_stats[t] = 0.f;
    int q = blockIdx.x >> 2;
    int4 v = *reinterpret_cast<int4*>(&g_bsum[t * 4]);
    int j0 = t * 4;
    int s = (j0 + 0 < q ? v.x : 0) + (j0 + 1 < q ? v.y : 0)
          + (j0 + 2 < q ? v.z : 0) + (j0 + 3 < q ? v.w : 0);
#pragma unroll
    for (int o = 16; o; o >>= 1) s += __shfl_xor_sync(0xffffffffu, s, o);
    if ((t & 31) == 0) sred[t >> 5] = s;
    __syncthreads();
    if (t == 0) {
        int r0 = 0;
#pragma unroll
        for (int w = 0; w < 8; w++) r0 += sred[w];
        sred[8] = r0;
    }
    __syncthreads();
    int S = sred[8];
    int i = blockIdx.x * 256 + t;
    int val = g_off[i] + S;
    g_off[i] = val;
    g_cur[i] = val;
    if (i == 0) g_off[N_NODES] = N_EDGES;
}

__global__ void k_place(const int* __restrict__ ei) {
    int e = blockIdx.x * blockDim.x + threadIdx.x;
    if (e >= N_EDGES) return;
    int s = __ldcs(&ei[e]);
    int d = __ldcs(&ei[N_EDGES + e]);
    int p = atomicAdd(&g_cur[d], 1);
    g_srt[p] = s;
}

// ---------------- layer 1: float4-packed x gather (1 LDG/neighbor) ----------------
__global__ void k_node1f(const float* __restrict__ Wl1, const float* __restrict__ Wr1,
                         const float* __restrict__ b1) {
    __shared__ float sWl[36], sWr[36], sb[12], sSum[24];
    int t = threadIdx.x;
    if (t < 36) { sWl[t] = Wl1[t]; sWr[t] = Wr1[t]; }
    if (t < 12) sb[t] = b1[t];
    if (t < 24) sSum[t] = 0.f;
    __syncthreads();
    int i = blockIdx.x * blockDim.x + t;
    int beg = g_off[i], end = g_off[i + 1];
    float a0 = 0.f, a1 = 0.f, a2 = 0.f;
    int p = beg;
    for (; p + 2 <= end; p += 2) {
        int s0 = __ldg(&g_srt[p]), s1 = __ldg(&g_srt[p + 1]);
        float4 u = __ldg(&g_xp[s0]);
        float4 w = __ldg(&g_xp[s1]);
        a0 += u.x + w.x; a1 += u.y + w.y; a2 += u.z + w.z;
    }
    if (p < end) {
        float4 u = __ldg(&g_xp[__ldg(&g_srt[p])]);
        a0 += u.x; a1 += u.y; a2 += u.z;
    }
    int dg = end - beg;
    float inv = dg > 0 ? 1.f / (float)dg : 0.f;
    float m0 = a0 * inv, m1 = a1 * inv, m2 = a2 * inv;
    float4 xs = __ldg(&g_xp[i]);
    float out[12];
#pragma unroll
    for (int k = 0; k < 12; k++) {
        float v = sb[k] + m0 * sWl[3 * k] + m1 * sWl[3 * k + 1] + m2 * sWl[3 * k + 2]
                        + xs.x * sWr[3 * k] + xs.y * sWr[3 * k + 1] + xs.z * sWr[3 * k + 2];
        out[k] = fmaxf(v, 0.f);
    }
    float4* hp = reinterpret_cast<float4*>(g_hA + (size_t)i * 12);
    __stcs(hp + 0, make_float4(out[0], out[1], out[2], out[3]));
    __stcs(hp + 1, make_float4(out[4], out[5], out[6], out[7]));
    __stcs(hp + 2, make_float4(out[8], out[9], out[10], out[11]));
    storeH(g_hHA, i, out);
#pragma unroll
    for (int k = 0; k < 12; k++) {
        float s = out[k], q = out[k] * out[k];
        warpsum(s); warpsum(q);
        if ((t & 31) == 0) { atomicAdd(&sSum[k], s); atomicAdd(&sSum[12 + k], q); }
    }
    __syncthreads();
    if (t < 24) atomicAdd(&g_stats[t], sSum[t]);
}

// ---------------- layers 2..8: fp16 gather (1x 256-bit LDG/neighbor) ----------------
template <int MODE>
__global__ void k_nodef(int in_sel, int out_sel,
                        const float* __restrict__ Wl, const float* __restrict__ Wr,
                        const float* __restrict__ bias,
                        const float* __restrict__ bng, const float* __restrict__ bnb,
                        int sin_off, int sout_off,
                        const float* __restrict__ linW, const float* __restrict__ linb) {
    const float*  h_in  = bufptr(in_sel);
    const __half* hH_in = bufptrH(in_sel);
    float*  h_out  = bufptr(out_sel);
    __half* hH_out = bufptrH(out_sel);
    __shared__ float sWl[144], sWr[144], sb[12], sa[12], sc[12], sSum[24], sLW[36], sLB[6];
    int t = threadIdx.x;
    if (t < 144) { sWl[t] = Wl[t]; sWr[t] = Wr[t]; }
    if (t < 12) {
        sb[t] = bias[t];
        float mean = g_stats[sin_off + t] * (1.f / N_NODES);
        float var  = g_stats[sin_off + 12 + t] * (1.f / N_NODES) - mean * mean;
        float a = bng[t] * rsqrtf(var + EPSV);
        sa[t] = a;
        sc[t] = bnb[t] - mean * a;
    }
    if (t < 24) sSum[t] = 0.f;
    if (MODE == 1) {
        if (t < 36) sLW[t] = linW[t];
        if (t < 6)  sLB[t] = linb[t];
    }
    __syncthreads();
    int i = blockIdx.x * blockDim.x + t;
    int beg = g_off[i], end = g_off[i + 1];
    float acc[12];
#pragma unroll
    for (int j = 0; j < 12; j++) acc[j] = 0.f;
    int p = beg;
    for (; p + 2 <= end; p += 2) {
        int s0 = __ldg(&g_srt[p]), s1 = __ldg(&g_srt[p + 1]);
        gathH(acc, hH_in, s0);
        gathH(acc, hH_in, s1);
    }
    if (p < end) gathH(acc, hH_in, __ldg(&g_srt[p]));

    const float4* hp = reinterpret_cast<const float4*>(h_in + (size_t)i * 12);
    float4 h0 = __ldcs(hp + 0), h1 = __ldcs(hp + 1), h2 = __ldcs(hp + 2);
    float hv[12] = {h0.x, h0.y, h0.z, h0.w, h1.x, h1.y, h1.z, h1.w, h2.x, h2.y, h2.z, h2.w};
    int dg = end - beg;
    float gate = dg > 0 ? 1.f : 0.f;
    float inv  = dg > 0 ? 1.f / (float)dg : 0.f;
    float m[12], hb[12];
#pragma unroll
    for (int j = 0; j < 12; j++) {
        m[j]  = acc[j] * inv * sa[j] + sc[j] * gate;   // bn(mean) fold; isolated -> 0
        hb[j] = hv[j] * sa[j] + sc[j];
    }
    float out[12];
#pragma unroll
    for (int k = 0; k < 12; k++) {
        float v = sb[k];
#pragma unroll
        for (int j = 0; j < 12; j++) v += m[j] * sWl[12 * k + j] + hb[j] * sWr[12 * k + j];
        out[k] = fmaxf(v, 0.f);
    }
    float4* op = reinterpret_cast<float4*>(h_out + (size_t)i * 12);
    __stcs(op + 0, make_float4(out[0], out[1], out[2], out[3]));
    __stcs(op + 1, make_float4(out[4], out[5], out[6], out[7]));
    __stcs(op + 2, make_float4(out[8], out[9], out[10], out[11]));
    storeH(hH_out, i, out);
    if (MODE == 0) {
#pragma unroll
        for (int k = 0; k < 12; k++) {
            float s = out[k], q = out[k] * out[k];
            warpsum(s); warpsum(q);
            if ((t & 31) == 0) { atomicAdd(&sSum[k], s); atomicAdd(&sSum[12 + k], q); }
        }
        __syncthreads();
        if (t < 24) atomicAdd(&g_stats[sout_off + t], sSum[t]);
    } else {
#pragma unroll
        for (int k = 0; k < 6; k++) {
            float za = sLB[k], zb = sLB[k];
#pragma unroll
            for (int j = 0; j < 6; j++) { za += out[j] * sLW[6 * k + j]; zb += out[6 + j] * sLW[6 * k + j]; }
            float s = za + zb, q = za * za + zb * zb;
            warpsum(s); warpsum(q);
            if ((t & 31) == 0) { atomicAdd(&sSum[k], s); atomicAdd(&sSum[6 + k], q); }
        }
        __syncthreads();
        if (t < 12) atomicAdd(&g_stats[sout_off + t], sSum[t]);
    }
}

// ---------------- head (all fp32, streaming) ----------------
template <int PASS>
__global__ void k_head(int in_sel, int out_sel,
                       const float* __restrict__ linW, const float* __restrict__ linb,
                       const float* __restrict__ g6, const float* __restrict__ b6,
                       int sin_off, int sout_off,
                       const float* __restrict__ oW, const float* __restrict__ ob,
                       float* __restrict__ outp) {
    const float* h_in = bufptr(in_sel);
    float* h_out = bufptr(out_sel);
    __shared__ float sLW[36], sLB[6], sa[6], sc[6], sSum[12], sOW[7];
    int t = threadIdx.x;
    if (t < 36) sLW[t] = linW[t];
    if (t < 6) {
        sLB[t] = linb[t];
        const float invM = 1.f / (2.f * N_NODES);
        float mean = g_stats[sin_off + t] * invM;
        float var  = g_stats[sin_off + 6 + t] * invM - mean * mean;
        float a = g6[t] * rsqrtf(var + EPSV);
        sa[t] = a;
        sc[t] = b6[t] - mean * a;
    }
    if (t < 12) sSum[t] = 0.f;
    if (PASS == 3) { if (t < 6) sOW[t] = oW[t]; if (t == 6) sOW[6] = ob[0]; }
    __syncthreads();
    int i = blockIdx.x * blockDim.x + t;
    const float4* hp = reinterpret_cast<const float4*>(h_in + (size_t)i * 12);
    float4 h0 = __ldcs(hp + 0), h1 = __ldcs(hp + 1), h2 = __ldcs(hp + 2);
    float hv[12] = {h0.x, h0.y, h0.z, h0.w, h1.x, h1.y, h1.z, h1.w, h2.x, h2.y, h2.z, h2.w};
    float r[12];
#pragma unroll
    for (int half = 0; half < 2; half++) {
#pragma unroll
        for (int k = 0; k < 6; k++) {
            float z = sLB[k];
#pragma unroll
            for (int j = 0; j < 6; j++) z += hv[6 * half + j] * sLW[6 * k + j];
            r[6 * half + k] = fmaxf(z * sa[k] + sc[k], 0.f);
        }
    }
    if (PASS < 3) {
        float4* op = reinterpret_cast<float4*>(h_out + (size_t)i * 12);
        __stcs(op + 0, make_float4(r[0], r[1], r[2], r[3]));
        __stcs(op + 1, make_float4(r[4], r[5], r[6], r[7]));
        __stcs(op + 2, make_float4(r[8], r[9], r[10], r[11]));
#pragma unroll
        for (int k = 0; k < 6; k++) {
            float za = sLB[k], zb = sLB[k];
#pragma unroll
            for (int j = 0; j < 6; j++) { za += r[j] * sLW[6 * k + j]; zb += r[6 + j] * sLW[6 * k + j]; }
            float s = za + zb, q = za * za + zb * zb;
            warpsum(s); warpsum(q);
            if ((t & 31) == 0) { atomicAdd(&sSum[k], s); atomicAdd(&sSum[6 + k], q); }
        }
        __syncthreads();
        if (t < 12) atomicAdd(&g_stats[sout_off + t], sSum[t]);
    } else {
        float oa = sOW[6], obv = sOW[6];
#pragma unroll
        for (int j = 0; j < 6; j++) { oa += r[j] * sOW[j]; obv += r[6 + j] * sOW[j]; }
        outp[2 * i]     = 1.f / (1.f + expf(-oa));
        outp[2 * i + 1] = 1.f / (1.f + expf(-obv));
    }
}

// ---------------- launch ----------------
extern "C" void kernel_launch(void* const* d_in, const int* in_sizes, int n_in,
                              void* d_out, int out_size) {
    const float* x    = (const float*)d_in[0];
    const int*   ei   = (const int*)d_in[1];
    const float* Wl1  = (const float*)d_in[2];
    const float* Wr1  = (const float*)d_in[3];
    const float* b1   = (const float*)d_in[4];
    const float* Wl   = (const float*)d_in[5];
    const float* Wr   = (const float*)d_in[6];
    const float* bb   = (const float*)d_in[7];
    const float* bng  = (const float*)d_in[8];
    const float* bnb  = (const float*)d_in[9];
    const float* linW = (const float*)d_in[10];
    const float* linb = (const float*)d_in[11];
    const float* g6   = (const float*)d_in[12];
    const float* b6   = (const float*)d_in[13];
    const float* oW   = (const float*)d_in[14];
    const float* ob   = (const float*)d_in[15];
    float* outp = (float*)d_out;

    const int EB = N_EDGES / 256;   // 16384
    const int NB = N_NODES / 256;   // 4096

    // CSR build (g_deg/g_stats zero at entry: load-time init or fused re-zeroing)
    k_degx<<<EB, 256>>>(ei, x);
    k_scanA<<<1024, 256>>>();       // also re-zeroes g_deg for next call
    k_scanB<<<NB, 256>>>();         // block 0 also re-zeroes g_stats
    k_place<<<EB, 256>>>(ei);

    // conv1 -> hA + fp16 mirror, stats slot 0
    k_node1f<<<NB, 256>>>(Wl1, Wr1, b1);

    int in_sel = 0, out_sel = 1;
    for (int i = 0; i < 7; i++) {
        int sin_off = 24 * i;
        if (i < 6) {
            k_nodef<0><<<NB, 256>>>(in_sel, out_sel, Wl + 144 * i, Wr + 144 * i, bb + 12 * i,
                                    bng + 12 * i, bnb + 12 * i, sin_off, 24 * (i + 1),
                                    linW, linb);
        } else {
            k_nodef<1><<<NB, 256>>>(in_sel, out_sel, Wl + 144 * i, Wr + 144 * i, bb + 12 * i,
                                    bng + 12 * i, bnb + 12 * i, sin_off, 7 * 24,
                                    linW, linb);
        }
        int tmp = in_sel; in_sel = out_sel; out_sel = tmp;
    }
    // conv8 output in hB (in_sel==1). Head: hB -> hA -> hB -> out.
    k_head<1><<<NB, 256>>>(1, 0, linW, linb, g6, b6, 168, 180, oW, ob, outp);
    k_head<2><<<NB, 256>>>(0, 1, linW, linb, g6, b6, 180, 192, oW, ob, outp);
    k_head<3><<<NB, 256>>>(1, 0, linW, linb, g6, b6, 192, 0, oW, ob, outp);
}

// round 13
// speedup vs baseline: 1.1100x; 1.0561x over previous
#include <cuda_runtime.h>
#include <cuda_fp16.h>
#include <math.h>

#define N_NODES 1048576
#define N_EDGES 4194304
#define EPSV 1e-5f
#define STATS_LEN (7*24 + 3*12)

// ---------------- scratch (static device globals; zero-init at load) ----------------
__device__ float  g_hA[N_NODES * 12];    // fp32 h: only conv8 output + head scratch
__device__ float  g_hB[N_NODES * 12];
__device__ __half g_hHA[N_NODES * 16];   // fp16 h (32B rows): conv-layer state
__device__ __half g_hHB[N_NODES * 16];
__device__ float4 g_xp[N_NODES];         // x packed to float4
__device__ int    g_deg[N_NODES];        // zeroed by k_scanA for next call
__device__ int    g_off[N_NODES + 1];
__device__ int    g_cur[N_NODES];
__device__ int    g_bsum[1024];
__device__ int    g_srt[N_EDGES];        // src ids grouped by dst (CSR adjacency)
__device__ float  g_stats[STATS_LEN];    // zeroed by k_scanB for next call

__device__ __forceinline__ float*  bufptr(int s)  { return s == 0 ? g_hA : g_hB; }
__device__ __forceinline__ __half* bufptrH(int s) { return s == 0 ? g_hHA : g_hHB; }

__device__ __forceinline__ void warpsum(float& v) {
#pragma unroll
    for (int o = 16; o; o >>= 1) v += __shfl_xor_sync(0xffffffffu, v, o);
}

// one 256-bit load of a 32B fp16 row -> 12 floats (words 6,7 padding)
__device__ __forceinline__ void loadH(float* dst, const __half* hH, int s) {
    const __half* r = hH + ((size_t)s << 4);
    float v0, v1, v2, v3, v4, v5, v6, v7;
    asm volatile("ld.global.nc.v8.f32 {%0,%1,%2,%3,%4,%5,%6,%7}, [%8];"
                 : "=f"(v0), "=f"(v1), "=f"(v2), "=f"(v3),
                   "=f"(v4), "=f"(v5), "=f"(v6), "=f"(v7)
                 : "l"(r));
    unsigned u;
    float2 f;
    u = __float_as_uint(v0); f = __half22float2(*reinterpret_cast<__half2*>(&u)); dst[0] = f.x; dst[1] = f.y;
    u = __float_as_uint(v1); f = __half22float2(*reinterpret_cast<__half2*>(&u)); dst[2] = f.x; dst[3] = f.y;
    u = __float_as_uint(v2); f = __half22float2(*reinterpret_cast<__half2*>(&u)); dst[4] = f.x; dst[5] = f.y;
    u = __float_as_uint(v3); f = __half22float2(*reinterpret_cast<__half2*>(&u)); dst[6] = f.x; dst[7] = f.y;
    u = __float_as_uint(v4); f = __half22float2(*reinterpret_cast<__half2*>(&u)); dst[8] = f.x; dst[9] = f.y;
    u = __float_as_uint(v5); f = __half22float2(*reinterpret_cast<__half2*>(&u)); dst[10] = f.x; dst[11] = f.y;
    (void)v6; (void)v7;
}

// gather-accumulate version
__device__ __forceinline__ void gathH(float* acc, const __half* hH, int s) {
    float tmp[12];
    loadH(tmp, hH, s);
#pragma unroll
    for (int j = 0; j < 12; j++) acc[j] += tmp[j];
}

// one 256-bit store of a 32B fp16 row (words 6,7 zero)
__device__ __forceinline__ void storeH(__half* hH, int i, const float* out) {
    __half* r = hH + ((size_t)i << 4);
    unsigned w0, w1, w2, w3, w4, w5;
    *reinterpret_cast<__half2*>(&w0) = __floats2half2_rn(out[0], out[1]);
    *reinterpret_cast<__half2*>(&w1) = __floats2half2_rn(out[2], out[3]);
    *reinterpret_cast<__half2*>(&w2) = __floats2half2_rn(out[4], out[5]);
    *reinterpret_cast<__half2*>(&w3) = __floats2half2_rn(out[6], out[7]);
    *reinterpret_cast<__half2*>(&w4) = __floats2half2_rn(out[8], out[9]);
    *reinterpret_cast<__half2*>(&w5) = __floats2half2_rn(out[10], out[11]);
    asm volatile("st.global.v8.f32 [%0], {%1,%2,%3,%4,%5,%6,%7,%8};"
                 :: "l"(r),
                    "f"(__uint_as_float(w0)), "f"(__uint_as_float(w1)),
                    "f"(__uint_as_float(w2)), "f"(__uint_as_float(w3)),
                    "f"(__uint_as_float(w4)), "f"(__uint_as_float(w5)),
                    "f"(0.f), "f"(0.f)
                 : "memory");
}

// ---------------- CSR build ----------------

__global__ void k_degx(const int* __restrict__ ei, const float* __restrict__ x) {
    int e = blockIdx.x * blockDim.x + threadIdx.x;
    if (e < N_EDGES) atomicAdd(&g_deg[__ldcs(&ei[N_EDGES + e])], 1);
    if (e < N_NODES) {
        g_xp[e] = make_float4(__ldcs(&x[3 * e]), __ldcs(&x[3 * e + 1]),
                              __ldcs(&x[3 * e + 2]), 0.f);
    }
}

// local exclusive scan: 1024 blocks x 1024 elements (256 thr x 4); re-zeroes g_deg
__global__ void k_scanA() {
    __shared__ int sh[256];
    int t = threadIdx.x;
    int base = blockIdx.x * 1024 + t * 4;
    int4 d = *reinterpret_cast<int4*>(&g_deg[base]);
    *reinterpret_cast<int4*>(&g_deg[base]) = make_int4(0, 0, 0, 0);
    int s1 = d.x + d.y, s2 = s1 + d.z, tot = s2 + d.w;
    sh[t] = tot;
    __syncthreads();
#pragma unroll
    for (int o = 1; o < 256; o <<= 1) {
        int v = (t >= o) ? sh[t - o] : 0;
        __syncthreads();
        sh[t] += v;
        __syncthreads();
    }
    int excl = sh[t] - tot;
    g_off[base + 0] = excl;
    g_off[base + 1] = excl + d.x;
    g_off[base + 2] = excl + s1;
    g_off[base + 3] = excl + s2;
    if (t == 255) g_bsum[blockIdx.x] = sh[255];
}

// finalize offsets; block 0 re-zeroes g_stats
__global__ void k_scanB() {
    __shared__ int sred[9];
    int t = threadIdx.x;
    if (blockIdx.x == 0 && t < STATS_LEN) g_stats[t] = 0.f;
    int q = blockIdx.x >> 2;
    int4 v = *reinterpret_cast<int4*>(&g_bsum[t * 4]);
    int j0 = t * 4;
    int s = (j0 + 0 < q ? v.x : 0) + (j0 + 1 < q ? v.y : 0)
          + (j0 + 2 < q ? v.z : 0) + (j0 + 3 < q ? v.w : 0);
#pragma unroll
    for (int o = 16; o; o >>= 1) s += __shfl_xor_sync(0xffffffffu, s, o);
    if ((t & 31) == 0) sred[t >> 5] = s;
    __syncthreads();
    if (t == 0) {
        int r0 = 0;
#pragma unroll
        for (int w = 0; w < 8; w++) r0 += sred[w];
        sred[8] = r0;
    }
    __syncthreads();
    int S = sred[8];
    int i = blockIdx.x * 256 + t;
    int val = g_off[i] + S;
    g_off[i] = val;
    g_cur[i] = val;
    if (i == 0) g_off[N_NODES] = N_EDGES;
}

__global__ void k_place(const int* __restrict__ ei) {
    int e = blockIdx.x * blockDim.x + threadIdx.x;
    if (e >= N_EDGES) return;
    int s = __ldcs(&ei[e]);
    int d = __ldcs(&ei[N_EDGES + e]);
    int p = atomicAdd(&g_cur[d], 1);
    g_srt[p] = s;
}

// ---------------- layer 1: float4-packed x gather; output fp16 mirror only -------
__global__ void k_node1f(const float* __restrict__ Wl1, const float* __restrict__ Wr1,
                         const float* __restrict__ b1) {
    __shared__ float sWl[36], sWr[36], sb[12], sSum[24];
    int t = threadIdx.x;
    if (t < 36) { sWl[t] = Wl1[t]; sWr[t] = Wr1[t]; }
    if (t < 12) sb[t] = b1[t];
    if (t < 24) sSum[t] = 0.f;
    __syncthreads();
    int i = blockIdx.x * blockDim.x + t;
    int beg = g_off[i], end = g_off[i + 1];
    float a0 = 0.f, a1 = 0.f, a2 = 0.f;
    int p = beg;
    for (; p + 2 <= end; p += 2) {
        int s0 = __ldg(&g_srt[p]), s1 = __ldg(&g_srt[p + 1]);
        float4 u = __ldg(&g_xp[s0]);
        float4 w = __ldg(&g_xp[s1]);
        a0 += u.x + w.x; a1 += u.y + w.y; a2 += u.z + w.z;
    }
    if (p < end) {
        float4 u = __ldg(&g_xp[__ldg(&g_srt[p])]);
        a0 += u.x; a1 += u.y; a2 += u.z;
    }
    int dg = end - beg;
    float inv = dg > 0 ? 1.f / (float)dg : 0.f;
    float m0 = a0 * inv, m1 = a1 * inv, m2 = a2 * inv;
    float4 xs = __ldg(&g_xp[i]);
    float out[12];
#pragma unroll
    for (int k = 0; k < 12; k++) {
        float v = sb[k] + m0 * sWl[3 * k] + m1 * sWl[3 * k + 1] + m2 * sWl[3 * k + 2]
                        + xs.x * sWr[3 * k] + xs.y * sWr[3 * k + 1] + xs.z * sWr[3 * k + 2];
        out[k] = fmaxf(v, 0.f);
    }
    storeH(g_hHA, i, out);
#pragma unroll
    for (int k = 0; k < 12; k++) {
        float s = out[k], q = out[k] * out[k];
        warpsum(s); warpsum(q);
        if ((t & 31) == 0) { atomicAdd(&sSum[k], s); atomicAdd(&sSum[12 + k], q); }
    }
    __syncthreads();
    if (t < 24) atomicAdd(&g_stats[t], sSum[t]);
}

// ---------------- layers 2..8: all-fp16 state, 256-bit row I/O ----------------
// MODE 0 (conv2..7): output fp16 mirror only, conv stats.
// MODE 1 (conv8):    output fp32 h_out (head chain needs fp32), head z1 stats.
template <int MODE>
__global__ void k_nodef(int in_sel, int out_sel,
                        const float* __restrict__ Wl, const float* __restrict__ Wr,
                        const float* __restrict__ bias,
                        const float* __restrict__ bng, const float* __restrict__ bnb,
                        int sin_off, int sout_off,
                        const float* __restrict__ linW, const float* __restrict__ linb) {
    const __half* hH_in = bufptrH(in_sel);
    float*  h_out  = bufptr(out_sel);
    __half* hH_out = bufptrH(out_sel);
    __shared__ float sWl[144], sWr[144], sb[12], sa[12], sc[12], sSum[24], sLW[36], sLB[6];
    int t = threadIdx.x;
    if (t < 144) { sWl[t] = Wl[t]; sWr[t] = Wr[t]; }
    if (t < 12) {
        sb[t] = bias[t];
        float mean = g_stats[sin_off + t] * (1.f / N_NODES);
        float var  = g_stats[sin_off + 12 + t] * (1.f / N_NODES) - mean * mean;
        float a = bng[t] * rsqrtf(var + EPSV);
        sa[t] = a;
        sc[t] = bnb[t] - mean * a;
    }
    if (t < 24) sSum[t] = 0.f;
    if (MODE == 1) {
        if (t < 36) sLW[t] = linW[t];
        if (t < 6)  sLB[t] = linb[t];
    }
    __syncthreads();
    int i = blockIdx.x * blockDim.x + t;
    int beg = g_off[i], end = g_off[i + 1];
    float acc[12];
#pragma unroll
    for (int j = 0; j < 12; j++) acc[j] = 0.f;
    int p = beg;
    for (; p + 2 <= end; p += 2) {
        int s0 = __ldg(&g_srt[p]), s1 = __ldg(&g_srt[p + 1]);
        gathH(acc, hH_in, s0);
        gathH(acc, hH_in, s1);
    }
    if (p < end) gathH(acc, hH_in, __ldg(&g_srt[p]));

    float hv[12];
    loadH(hv, hH_in, i);            // self row from fp16 mirror (1 wavefront)
    int dg = end - beg;
    float gate = dg > 0 ? 1.f : 0.f;
    float inv  = dg > 0 ? 1.f / (float)dg : 0.f;
    float m[12], hb[12];
#pragma unroll
    for (int j = 0; j < 12; j++) {
        m[j]  = acc[j] * inv * sa[j] + sc[j] * gate;   // bn(mean) fold; isolated -> 0
        hb[j] = hv[j] * sa[j] + sc[j];
    }
    float out[12];
#pragma unroll
    for (int k = 0; k < 12; k++) {
        float v = sb[k];
#pragma unroll
        for (int j = 0; j < 12; j++) v += m[j] * sWl[12 * k + j] + hb[j] * sWr[12 * k + j];
        out[k] = fmaxf(v, 0.f);
    }
    if (MODE == 0) {
        storeH(hH_out, i, out);
#pragma unroll
        for (int k = 0; k < 12; k++) {
            float s = out[k], q = out[k] * out[k];
            warpsum(s); warpsum(q);
            if ((t & 31) == 0) { atomicAdd(&sSum[k], s); atomicAdd(&sSum[12 + k], q); }
        }
        __syncthreads();
        if (t < 24) atomicAdd(&g_stats[sout_off + t], sSum[t]);
    } else {
        float4* op = reinterpret_cast<float4*>(h_out + (size_t)i * 12);
        __stcs(op + 0, make_float4(out[0], out[1], out[2], out[3]));
        __stcs(op + 1, make_float4(out[4], out[5], out[6], out[7]));
        __stcs(op + 2, make_float4(out[8], out[9], out[10], out[11]));
#pragma unroll
        for (int k = 0; k < 6; k++) {
            float za = sLB[k], zb = sLB[k];
#pragma unroll
            for (int j = 0; j < 6; j++) { za += out[j] * sLW[6 * k + j]; zb += out[6 + j] * sLW[6 * k + j]; }
            float s = za + zb, q = za * za + zb * zb;
            warpsum(s); warpsum(q);
            if ((t & 31) == 0) { atomicAdd(&sSum[k], s); atomicAdd(&sSum[6 + k], q); }
        }
        __syncthreads();
        if (t < 12) atomicAdd(&g_stats[sout_off + t], sSum[t]);
    }
}

// ---------------- head (all fp32, streaming) ----------------
template <int PASS>
__global__ void k_head(int in_sel, int out_sel,
                       const float* __restrict__ linW, const float* __restrict__ linb,
                       const float* __restrict__ g6, const float* __restrict__ b6,
                       int sin_off, int sout_off,
                       const float* __restrict__ oW, const float* __restrict__ ob,
                       float* __restrict__ outp) {
    const float* h_in = bufptr(in_sel);
    float* h_out = bufptr(out_sel);
    __shared__ float sLW[36], sLB[6], sa[6], sc[6], sSum[12], sOW[7];
    int t = threadIdx.x;
    if (t < 36) sLW[t] = linW[t];
    if (t < 6) {
        sLB[t] = linb[t];
        const float invM = 1.f / (2.f * N_NODES);
        float mean = g_stats[sin_off + t] * invM;
        float var  = g_stats[sin_off + 6 + t] * invM - mean * mean;
        float a = g6[t] * rsqrtf(var + EPSV);
        sa[t] = a;
        sc[t] = b6[t] - mean * a;
    }
    if (t < 12) sSum[t] = 0.f;
    if (PASS == 3) { if (t < 6) sOW[t] = oW[t]; if (t == 6) sOW[6] = ob[0]; }
    __syncthreads();
    int i = blockIdx.x * blockDim.x + t;
    const float4* hp = reinterpret_cast<const float4*>(h_in + (size_t)i * 12);
    float4 h0 = __ldcs(hp + 0), h1 = __ldcs(hp + 1), h2 = __ldcs(hp + 2);
    float hv[12] = {h0.x, h0.y, h0.z, h0.w, h1.x, h1.y, h1.z, h1.w, h2.x, h2.y, h2.z, h2.w};
    float r[12];
#pragma unroll
    for (int half = 0; half < 2; half++) {
#pragma unroll
        for (int k = 0; k < 6; k++) {
            float z = sLB[k];
#pragma unroll
            for (int j = 0; j < 6; j++) z += hv[6 * half + j] * sLW[6 * k + j];
            r[6 * half + k] = fmaxf(z * sa[k] + sc[k], 0.f);
        }
    }
    if (PASS < 3) {
        float4* op = reinterpret_cast<float4*>(h_out + (size_t)i * 12);
        __stcs(op + 0, make_float4(r[0], r[1], r[2], r[3]));
        __stcs(op + 1, make_float4(r[4], r[5], r[6], r[7]));
        __stcs(op + 2, make_float4(r[8], r[9], r[10], r[11]));
#pragma unroll
        for (int k = 0; k < 6; k++) {
            float za = sLB[k], zb = sLB[k];
#pragma unroll
            for (int j = 0; j < 6; j++) { za += r[j] * sLW[6 * k + j]; zb += r[6 + j] * sLW[6 * k + j]; }
            float s = za + zb, q = za * za + zb * zb;
            warpsum(s); warpsum(q);
            if ((t & 31) == 0) { atomicAdd(&sSum[k], s); atomicAdd(&sSum[6 + k], q); }
        }
        __syncthreads();
        if (t < 12) atomicAdd(&g_stats[sout_off + t], sSum[t]);
    } else {
        float oa = sOW[6], obv = sOW[6];
#pragma unroll
        for (int j = 0; j < 6; j++) { oa += r[j] * sOW[j]; obv += r[6 + j] * sOW[j]; }
        outp[2 * i]     = 1.f / (1.f + expf(-oa));
        outp[2 * i + 1] = 1.f / (1.f + expf(-obv));
    }
}

// ---------------- launch ----------------
extern "C" void kernel_launch(void* const* d_in, const int* in_sizes, int n_in,
                              void* d_out, int out_size) {
    const float* x    = (const float*)d_in[0];
    const int*   ei   = (const int*)d_in[1];
    const float* Wl1  = (const float*)d_in[2];
    const float* Wr1  = (const float*)d_in[3];
    const float* b1   = (const float*)d_in[4];
    const float* Wl   = (const float*)d_in[5];
    const float* Wr   = (const float*)d_in[6];
    const float* bb   = (const float*)d_in[7];
    const float* bng  = (const float*)d_in[8];
    const float* bnb  = (const float*)d_in[9];
    const float* linW = (const float*)d_in[10];
    const float* linb = (const float*)d_in[11];
    const float* g6   = (const float*)d_in[12];
    const float* b6   = (const float*)d_in[13];
    const float* oW   = (const float*)d_in[14];
    const float* ob   = (const float*)d_in[15];
    float* outp = (float*)d_out;

    const int EB = N_EDGES / 256;   // 16384
    const int NB = N_NODES / 256;   // 4096

    // CSR build (g_deg/g_stats zero at entry: load-time init or fused re-zeroing)
    k_degx<<<EB, 256>>>(ei, x);
    k_scanA<<<1024, 256>>>();       // also re-zeroes g_deg for next call
    k_scanB<<<NB, 256>>>();         // block 0 also re-zeroes g_stats
    k_place<<<EB, 256>>>(ei);

    // conv1 -> hHA (fp16), stats slot 0
    k_node1f<<<NB, 256>>>(Wl1, Wr1, b1);

    int in_sel = 0, out_sel = 1;
    for (int i = 0; i < 7; i++) {
        int sin_off = 24 * i;
        if (i < 6) {
            k_nodef<0><<<NB, 256>>>(in_sel, out_sel, Wl + 144 * i, Wr + 144 * i, bb + 12 * i,
                                    bng + 12 * i, bnb + 12 * i, sin_off, 24 * (i + 1),
                                    linW, linb);
        } else {
            k_nodef<1><<<NB, 256>>>(in_sel, out_sel, Wl + 144 * i, Wr + 144 * i, bb + 12 * i,
                                    bng + 12 * i, bnb + 12 * i, sin_off, 7 * 24,
                                    linW, linb);
        }
        int tmp = in_sel; in_sel = out_sel; out_sel = tmp;
    }
    // conv8 output (fp32) in g_hB (out_sel of i=6 was 1). Head: hB -> hA -> hB -> out.
    k_head<1><<<NB, 256>>>(1, 0, linW, linb, g6, b6, 168, 180, oW, ob, outp);
    k_head<2><<<NB, 256>>>(0, 1, linW, linb, g6, b6, 180, 192, oW, ob, outp);
    k_head<3><<<NB, 256>>>(1, 0, linW, linb, g6, b6, 192, 0, oW, ob, outp);
}

// round 14
// speedup vs baseline: 1.3573x; 1.2228x over previous
#include <cuda_runtime.h>
#include <cuda_fp16.h>
#include <math.h>

#define N_NODES 1048576
#define N_EDGES 4194304
#define EPSV 1e-5f
#define STATS_LEN (7*24 + 3*12)

// ---------------- scratch (static device globals; zero-init at load) ----------------
__device__ float  g_hA[N_NODES * 12];    // fp32 h: only conv8 output + head scratch
__device__ float  g_hB[N_NODES * 12];
__device__ __half g_hHA[N_NODES * 16];   // fp16 h (32B rows): conv-layer state
__device__ __half g_hHB[N_NODES * 16];
__device__ float4 g_xp[N_NODES];         // x packed to float4
__device__ int    g_deg[N_NODES];        // zeroed by k_scanA for next call
__device__ int    g_off[N_NODES + 1];
__device__ int    g_cur[N_NODES];
__device__ int    g_bsum[1024];
__device__ int    g_srt[N_EDGES];        // src ids grouped by dst (CSR adjacency)
__device__ float  g_stats[STATS_LEN];    // zeroed by k_scanB for next call

__device__ __forceinline__ float*  bufptr(int s)  { return s == 0 ? g_hA : g_hB; }
__device__ __forceinline__ __half* bufptrH(int s) { return s == 0 ? g_hHA : g_hHB; }

// ---- two-phase block stats reduction over 12 shared rows (stride-13 layout) ----
// Phase 1 (caller): sOut[t*13 + k] = value_k, k=0..11, then call this.
// Phase 2: 96 threads, 8 per channel, bank-rotated conflict-free reads.
// SQ=true: emits sum -> [base+c], sumsq -> [base+12+c] (c=0..11).
// SQ=false: rows already hold s (rows 0..5) and q (rows 6..11); emits row sums -> [base+c].
template <bool SQ>
__device__ __forceinline__ void stats_reduce(const float* sOut, int t, int base_out) {
    __syncthreads();
    if (t < 96) {
        int c = t >> 3, g = t & 7;
        float s = 0.f, q = 0.f;
#pragma unroll
        for (int jj = 0; jj < 32; jj++) {
            int j = (jj + 4 * g) & 31;
            float v = sOut[(g * 32 + j) * 13 + c];
            s += v;
            if (SQ) q += v * v;
        }
#pragma unroll
        for (int o = 4; o; o >>= 1) {
            s += __shfl_down_sync(0xffffffffu, s, o);
            if (SQ) q += __shfl_down_sync(0xffffffffu, q, o);
        }
        if (g == 0) {
            atomicAdd(&g_stats[base_out + c], s);
            if (SQ) atomicAdd(&g_stats[base_out + 12 + c], q);
        }
    }
}

// one 256-bit load of a 32B fp16 row -> 12 floats (words 6,7 padding)
__device__ __forceinline__ void loadH(float* dst, const __half* hH, int s) {
    const __half* r = hH + ((size_t)s << 4);
    float v0, v1, v2, v3, v4, v5, v6, v7;
    asm volatile("ld.global.nc.v8.f32 {%0,%1,%2,%3,%4,%5,%6,%7}, [%8];"
                 : "=f"(v0), "=f"(v1), "=f"(v2), "=f"(v3),
                   "=f"(v4), "=f"(v5), "=f"(v6), "=f"(v7)
                 : "l"(r));
    unsigned u;
    float2 f;
    u = __float_as_uint(v0); f = __half22float2(*reinterpret_cast<__half2*>(&u)); dst[0] = f.x; dst[1] = f.y;
    u = __float_as_uint(v1); f = __half22float2(*reinterpret_cast<__half2*>(&u)); dst[2] = f.x; dst[3] = f.y;
    u = __float_as_uint(v2); f = __half22float2(*reinterpret_cast<__half2*>(&u)); dst[4] = f.x; dst[5] = f.y;
    u = __float_as_uint(v3); f = __half22float2(*reinterpret_cast<__half2*>(&u)); dst[6] = f.x; dst[7] = f.y;
    u = __float_as_uint(v4); f = __half22float2(*reinterpret_cast<__half2*>(&u)); dst[8] = f.x; dst[9] = f.y;
    u = __float_as_uint(v5); f = __half22float2(*reinterpret_cast<__half2*>(&u)); dst[10] = f.x; dst[11] = f.y;
    (void)v6; (void)v7;
}

// gather-accumulate version
__device__ __forceinline__ void gathH(float* acc, const __half* hH, int s) {
    float tmp[12];
    loadH(tmp, hH, s);
#pragma unroll
    for (int j = 0; j < 12; j++) acc[j] += tmp[j];
}

// one 256-bit store of a 32B fp16 row (words 6,7 zero)
__device__ __forceinline__ void storeH(__half* hH, int i, const float* out) {
    __half* r = hH + ((size_t)i << 4);
    unsigned w0, w1, w2, w3, w4, w5;
    *reinterpret_cast<__half2*>(&w0) = __floats2half2_rn(out[0], out[1]);
    *reinterpret_cast<__half2*>(&w1) = __floats2half2_rn(out[2], out[3]);
    *reinterpret_cast<__half2*>(&w2) = __floats2half2_rn(out[4], out[5]);
    *reinterpret_cast<__half2*>(&w3) = __floats2half2_rn(out[6], out[7]);
    *reinterpret_cast<__half2*>(&w4) = __floats2half2_rn(out[8], out[9]);
    *reinterpret_cast<__half2*>(&w5) = __floats2half2_rn(out[10], out[11]);
    asm volatile("st.global.v8.f32 [%0], {%1,%2,%3,%4,%5,%6,%7,%8};"
                 :: "l"(r),
                    "f"(__uint_as_float(w0)), "f"(__uint_as_float(w1)),
                    "f"(__uint_as_float(w2)), "f"(__uint_as_float(w3)),
                    "f"(__uint_as_float(w4)), "f"(__uint_as_float(w5)),
                    "f"(0.f), "f"(0.f)
                 : "memory");
}

// ---------------- CSR build ----------------

__global__ void k_degx(const int* __restrict__ ei, const float* __restrict__ x) {
    int e = blockIdx.x * blockDim.x + threadIdx.x;
    if (e < N_EDGES) atomicAdd(&g_deg[__ldcs(&ei[N_EDGES + e])], 1);
    if (e < N_NODES) {
        g_xp[e] = make_float4(__ldcs(&x[3 * e]), __ldcs(&x[3 * e + 1]),
                              __ldcs(&x[3 * e + 2]), 0.f);
    }
}

// local exclusive scan: 1024 blocks x 1024 elements (256 thr x 4); re-zeroes g_deg
__global__ void k_scanA() {
    __shared__ int sh[256];
    int t = threadIdx.x;
    int base = blockIdx.x * 1024 + t * 4;
    int4 d = *reinterpret_cast<int4*>(&g_deg[base]);
    *reinterpret_cast<int4*>(&g_deg[base]) = make_int4(0, 0, 0, 0);
    int s1 = d.x + d.y, s2 = s1 + d.z, tot = s2 + d.w;
    sh[t] = tot;
    __syncthreads();
#pragma unroll
    for (int o = 1; o < 256; o <<= 1) {
        int v = (t >= o) ? sh[t - o] : 0;
        __syncthreads();
        sh[t] += v;
        __syncthreads();
    }
    int excl = sh[t] - tot;
    g_off[base + 0] = excl;
    g_off[base + 1] = excl + d.x;
    g_off[base + 2] = excl + s1;
    g_off[base + 3] = excl + s2;
    if (t == 255) g_bsum[blockIdx.x] = sh[255];
}

// finalize offsets; block 0 re-zeroes g_stats
__global__ void k_scanB() {
    __shared__ int sred[9];
    int t = threadIdx.x;
    if (blockIdx.x == 0 && t < STATS_LEN) g_stats[t] = 0.f;
    int q = blockIdx.x >> 2;
    int4 v = *reinterpret_cast<int4*>(&g_bsum[t * 4]);
    int j0 = t * 4;
    int s = (j0 + 0 < q ? v.x : 0) + (j0 + 1 < q ? v.y : 0)
          + (j0 + 2 < q ? v.z : 0) + (j0 + 3 < q ? v.w : 0);
#pragma unroll
    for (int o = 16; o; o >>= 1) s += __shfl_xor_sync(0xffffffffu, s, o);
    if ((t & 31) == 0) sred[t >> 5] = s;
    __syncthreads();
    if (t == 0) {
        int r0 = 0;
#pragma unroll
        for (int w = 0; w < 8; w++) r0 += sred[w];
        sred[8] = r0;
    }
    __syncthreads();
    int S = sred[8];
    int i = blockIdx.x * 256 + t;
    int val = g_off[i] + S;
    g_off[i] = val;
    g_cur[i] = val;
    if (i == 0) g_off[N_NODES] = N_EDGES;
}

__global__ void k_place(const int* __restrict__ ei) {
    int e = blockIdx.x * blockDim.x + threadIdx.x;
    if (e >= N_EDGES) return;
    int s = __ldcs(&ei[e]);
    int d = __ldcs(&ei[N_EDGES + e]);
    int p = atomicAdd(&g_cur[d], 1);
    g_srt[p] = s;
}

// ---------------- layer 1: float4-packed x gather; output fp16 mirror only -------
__global__ void k_node1f(const float* __restrict__ Wl1, const float* __restrict__ Wr1,
                         const float* __restrict__ b1) {
    __shared__ float sWl[36], sWr[36], sb[12];
    __shared__ float sOut[256 * 13];
    int t = threadIdx.x;
    if (t < 36) { sWl[t] = Wl1[t]; sWr[t] = Wr1[t]; }
    if (t < 12) sb[t] = b1[t];
    __syncthreads();
    int i = blockIdx.x * blockDim.x + t;
    int beg = g_off[i], end = g_off[i + 1];
    float a0 = 0.f, a1 = 0.f, a2 = 0.f;
    int p = beg;
    for (; p + 2 <= end; p += 2) {
        int s0 = __ldg(&g_srt[p]), s1 = __ldg(&g_srt[p + 1]);
        float4 u = __ldg(&g_xp[s0]);
        float4 w = __ldg(&g_xp[s1]);
        a0 += u.x + w.x; a1 += u.y + w.y; a2 += u.z + w.z;
    }
    if (p < end) {
        float4 u = __ldg(&g_xp[__ldg(&g_srt[p])]);
        a0 += u.x; a1 += u.y; a2 += u.z;
    }
    int dg = end - beg;
    float inv = dg > 0 ? 1.f / (float)dg : 0.f;
    float m0 = a0 * inv, m1 = a1 * inv, m2 = a2 * inv;
    float4 xs = __ldg(&g_xp[i]);
    float out[12];
#pragma unroll
    for (int k = 0; k < 12; k++) {
        float v = sb[k] + m0 * sWl[3 * k] + m1 * sWl[3 * k + 1] + m2 * sWl[3 * k + 2]
                        + xs.x * sWr[3 * k] + xs.y * sWr[3 * k + 1] + xs.z * sWr[3 * k + 2];
        out[k] = fmaxf(v, 0.f);
    }
    storeH(g_hHA, i, out);
#pragma unroll
    for (int k = 0; k < 12; k++) sOut[t * 13 + k] = out[k];
    stats_reduce<true>(sOut, t, 0);
}

// ---------------- layers 2..8: all-fp16 state, 256-bit row I/O ----------------
// MODE 0 (conv2..7): output fp16 mirror only, conv stats.
// MODE 1 (conv8):    output fp32 h_out (head chain needs fp32), head z1 stats.
template <int MODE>
__global__ void k_nodef(int in_sel, int out_sel,
                        const float* __restrict__ Wl, const float* __restrict__ Wr,
                        const float* __restrict__ bias,
                        const float* __restrict__ bng, const float* __restrict__ bnb,
                        int sin_off, int sout_off,
                        const float* __restrict__ linW, const float* __restrict__ linb) {
    const __half* hH_in = bufptrH(in_sel);
    float*  h_out  = bufptr(out_sel);
    __half* hH_out = bufptrH(out_sel);
    __shared__ float sWl[144], sWr[144], sb[12], sa[12], sc[12], sLW[36], sLB[6];
    __shared__ float sOut[256 * 13];
    int t = threadIdx.x;
    if (t < 144) { sWl[t] = Wl[t]; sWr[t] = Wr[t]; }
    if (t < 12) {
        sb[t] = bias[t];
        float mean = g_stats[sin_off + t] * (1.f / N_NODES);
        float var  = g_stats[sin_off + 12 + t] * (1.f / N_NODES) - mean * mean;
        float a = bng[t] * rsqrtf(var + EPSV);
        sa[t] = a;
        sc[t] = bnb[t] - mean * a;
    }
    if (MODE == 1) {
        if (t < 36) sLW[t] = linW[t];
        if (t < 6)  sLB[t] = linb[t];
    }
    __syncthreads();
    int i = blockIdx.x * blockDim.x + t;
    int beg = g_off[i], end = g_off[i + 1];
    float acc[12];
#pragma unroll
    for (int j = 0; j < 12; j++) acc[j] = 0.f;
    int p = beg;
    for (; p + 2 <= end; p += 2) {
        int s0 = __ldg(&g_srt[p]), s1 = __ldg(&g_srt[p + 1]);
        gathH(acc, hH_in, s0);
        gathH(acc, hH_in, s1);
    }
    if (p < end) gathH(acc, hH_in, __ldg(&g_srt[p]));

    float hv[12];
    loadH(hv, hH_in, i);            // self row from fp16 mirror (1 wavefront)
    int dg = end - beg;
    float gate = dg > 0 ? 1.f : 0.f;
    float inv  = dg > 0 ? 1.f / (float)dg : 0.f;
    float m[12], hb[12];
#pragma unroll
    for (int j = 0; j < 12; j++) {
        m[j]  = acc[j] * inv * sa[j] + sc[j] * gate;   // bn(mean) fold; isolated -> 0
        hb[j] = hv[j] * sa[j] + sc[j];
    }
    float out[12];
#pragma unroll
    for (int k = 0; k < 12; k++) {
        float v = sb[k];
#pragma unroll
        for (int j = 0; j < 12; j++) v += m[j] * sWl[12 * k + j] + hb[j] * sWr[12 * k + j];
        out[k] = fmaxf(v, 0.f);
    }
    if (MODE == 0) {
        storeH(hH_out, i, out);
#pragma unroll
        for (int k = 0; k < 12; k++) sOut[t * 13 + k] = out[k];
        stats_reduce<true>(sOut, t, sout_off);
    } else {
        float4* op = reinterpret_cast<float4*>(h_out + (size_t)i * 12);
        __stcs(op + 0, make_float4(out[0], out[1], out[2], out[3]));
        __stcs(op + 1, make_float4(out[4], out[5], out[6], out[7]));
        __stcs(op + 2, make_float4(out[8], out[9], out[10], out[11]));
#pragma unroll
        for (int k = 0; k < 6; k++) {
            float za = sLB[k], zb = sLB[k];
#pragma unroll
            for (int j = 0; j < 6; j++) { za += out[j] * sLW[6 * k + j]; zb += out[6 + j] * sLW[6 * k + j]; }
            sOut[t * 13 + k]     = za + zb;
            sOut[t * 13 + 6 + k] = za * za + zb * zb;
        }
        stats_reduce<false>(sOut, t, sout_off);
    }
}

// ---------------- head (all fp32, streaming) ----------------
template <int PASS>
__global__ void k_head(int in_sel, int out_sel,
                       const float* __restrict__ linW, const float* __restrict__ linb,
                       const float* __restrict__ g6, const float* __restrict__ b6,
                       int sin_off, int sout_off,
                       const float* __restrict__ oW, const float* __restrict__ ob,
                       float* __restrict__ outp) {
    const float* h_in = bufptr(in_sel);
    float* h_out = bufptr(out_sel);
    __shared__ float sLW[36], sLB[6], sa[6], sc[6], sOW[7];
    __shared__ float sOut[256 * 13];
    int t = threadIdx.x;
    if (t < 36) sLW[t] = linW[t];
    if (t < 6) {
        sLB[t] = linb[t];
        const float invM = 1.f / (2.f * N_NODES);
        float mean = g_stats[sin_off + t] * invM;
        float var  = g_stats[sin_off + 6 + t] * invM - mean * mean;
        float a = g6[t] * rsqrtf(var + EPSV);
        sa[t] = a;
        sc[t] = b6[t] - mean * a;
    }
    if (PASS == 3) { if (t < 6) sOW[t] = oW[t]; if (t == 6) sOW[6] = ob[0]; }
    __syncthreads();
    int i = blockIdx.x * blockDim.x + t;
    const float4* hp = reinterpret_cast<const float4*>(h_in + (size_t)i * 12);
    float4 h0 = __ldcs(hp + 0), h1 = __ldcs(hp + 1), h2 = __ldcs(hp + 2);
    float hv[12] = {h0.x, h0.y, h0.z, h0.w, h1.x, h1.y, h1.z, h1.w, h2.x, h2.y, h2.z, h2.w};
    float r[12];
#pragma unroll
    for (int half = 0; half < 2; half++) {
#pragma unroll
        for (int k = 0; k < 6; k++) {
            float z = sLB[k];
#pragma unroll
            for (int j = 0; j < 6; j++) z += hv[6 * half + j] * sLW[6 * k + j];
            r[6 * half + k] = fmaxf(z * sa[k] + sc[k], 0.f);
        }
    }
    if (PASS < 3) {
        float4* op = reinterpret_cast<float4*>(h_out + (size_t)i * 12);
        __stcs(op + 0, make_float4(r[0], r[1], r[2], r[3]));
        __stcs(op + 1, make_float4(r[4], r[5], r[6], r[7]));
        __stcs(op + 2, make_float4(r[8], r[9], r[10], r[11]));
#pragma unroll
        for (int k = 0; k < 6; k++) {
            float za = sLB[k], zb = sLB[k];
#pragma unroll
            for (int j = 0; j < 6; j++) { za += r[j] * sLW[6 * k + j]; zb += r[6 + j] * sLW[6 * k + j]; }
            sOut[t * 13 + k]     = za + zb;
            sOut[t * 13 + 6 + k] = za * za + zb * zb;
        }
        stats_reduce<false>(sOut, t, sout_off);
    } else {
        float oa = sOW[6], obv = sOW[6];
#pragma unroll
        for (int j = 0; j < 6; j++) { oa += r[j] * sOW[j]; obv += r[6 + j] * sOW[j]; }
        outp[2 * i]     = 1.f / (1.f + expf(-oa));
        outp[2 * i + 1] = 1.f / (1.f + expf(-obv));
    }
}

// ---------------- launch ----------------
extern "C" void kernel_launch(void* const* d_in, const int* in_sizes, int n_in,
                              void* d_out, int out_size) {
    const float* x    = (const float*)d_in[0];
    const int*   ei   = (const int*)d_in[1];
    const float* Wl1  = (const float*)d_in[2];
    const float* Wr1  = (const float*)d_in[3];
    const float* b1   = (const float*)d_in[4];
    const float* Wl   = (const float*)d_in[5];
    const float* Wr   = (const float*)d_in[6];
    const float* bb   = (const float*)d_in[7];
    const float* bng  = (const float*)d_in[8];
    const float* bnb  = (const float*)d_in[9];
    const float* linW = (const float*)d_in[10];
    const float* linb = (const float*)d_in[11];
    const float* g6   = (const float*)d_in[12];
    const float* b6   = (const float*)d_in[13];
    const float* oW   = (const float*)d_in[14];
    const float* ob   = (const float*)d_in[15];
    float* outp = (float*)d_out;

    const int EB = N_EDGES / 256;   // 16384
    const int NB = N_NODES / 256;   // 4096

    // CSR build (g_deg/g_stats zero at entry: load-time init or fused re-zeroing)
    k_degx<<<EB, 256>>>(ei, x);
    k_scanA<<<1024, 256>>>();       // also re-zeroes g_deg for next call
    k_scanB<<<NB, 256>>>();         // block 0 also re-zeroes g_stats
    k_place<<<EB, 256>>>(ei);

    // conv1 -> hHA (fp16), stats slot 0
    k_node1f<<<NB, 256>>>(Wl1, Wr1, b1);

    int in_sel = 0, out_sel = 1;
    for (int i = 0; i < 7; i++) {
        int sin_off = 24 * i;
        if (i < 6) {
            k_nodef<0><<<NB, 256>>>(in_sel, out_sel, Wl + 144 * i, Wr + 144 * i, bb + 12 * i,
                                    bng + 12 * i, bnb + 12 * i, sin_off, 24 * (i + 1),
                                    linW, linb);
        } else {
            k_nodef<1><<<NB, 256>>>(in_sel, out_sel, Wl + 144 * i, Wr + 144 * i, bb + 12 * i,
                                    bng + 12 * i, bnb + 12 * i, sin_off, 7 * 24,
                                    linW, linb);
        }
        int tmp = in_sel; in_sel = out_sel; out_sel = tmp;
    }
    // conv8 output (fp32) in g_hB. Head: hB -> hA -> hB -> out.
    k_head<1><<<NB, 256>>>(1, 0, linW, linb, g6, b6, 168, 180, oW, ob, outp);
    k_head<2><<<NB, 256>>>(0, 1, linW, linb, g6, b6, 180, 192, oW, ob, outp);
    k_head<3><<<NB, 256>>>(1, 0, linW, linb, g6, b6, 192, 0, oW, ob, outp);
}

// round 15
// speedup vs baseline: 1.4101x; 1.0389x over previous
#include <cuda_runtime.h>
#include <cuda_fp16.h>
#include <math.h>

#define N_NODES 1048576
#define N_EDGES 4194304
#define EPSV 1e-5f
#define STATS_LEN (7*24 + 3*12)

// ---------------- scratch (static device globals; zero-init at load) ----------------
__device__ float  g_hA[N_NODES * 12];    // fp32 h: only conv8 output + head scratch
__device__ float  g_hB[N_NODES * 12];
__device__ __half g_hHA[N_NODES * 16];   // fp16 h (32B rows): conv-layer state
__device__ __half g_hHB[N_NODES * 16];
__device__ float4 g_xp[N_NODES];         // x packed to float4
__device__ int    g_deg[N_NODES];        // zeroed by k_scanA for next call
__device__ int    g_off[N_NODES + 1];
__device__ int    g_cur[N_NODES];
__device__ int    g_bsum[1024];
__device__ int    g_srt[N_EDGES];        // src ids grouped by dst (CSR adjacency)
__device__ float  g_stats[STATS_LEN];    // zeroed by k_scanB for next call

__device__ __forceinline__ float*  bufptr(int s)  { return s == 0 ? g_hA : g_hB; }
__device__ __forceinline__ __half* bufptrH(int s) { return s == 0 ? g_hHA : g_hHB; }

// ---- packed dual-fp32 FMA (Blackwell f32x2 pipe; exact fp32 on both lanes) ----
__device__ __forceinline__ unsigned long long pack2(float x, float y) {
    unsigned long long r;
    asm("mov.b64 %0, {%1, %2};" : "=l"(r) : "f"(x), "f"(y));
    return r;
}
__device__ __forceinline__ void unpack2(unsigned long long v, float& x, float& y) {
    asm("mov.b64 {%0, %1}, %2;" : "=f"(x), "=f"(y) : "l"(v));
}
__device__ __forceinline__ void fma2(unsigned long long& d, unsigned long long a,
                                     unsigned long long b) {
    asm("fma.rn.f32x2 %0, %1, %2, %3;" : "=l"(d) : "l"(a), "l"(b), "l"(d));
}

// ---- two-phase block stats reduction over 12 shared rows (stride-13 layout) ----
template <bool SQ>
__device__ __forceinline__ void stats_reduce(const float* sOut, int t, int base_out) {
    __syncthreads();
    if (t < 96) {
        int c = t >> 3, g = t & 7;
        float s = 0.f, q = 0.f;
#pragma unroll
        for (int jj = 0; jj < 32; jj++) {
            int j = (jj + 4 * g) & 31;
            float v = sOut[(g * 32 + j) * 13 + c];
            s += v;
            if (SQ) q += v * v;
        }
#pragma unroll
        for (int o = 4; o; o >>= 1) {
            s += __shfl_down_sync(0xffffffffu, s, o);
            if (SQ) q += __shfl_down_sync(0xffffffffu, q, o);
        }
        if (g == 0) {
            atomicAdd(&g_stats[base_out + c], s);
            if (SQ) atomicAdd(&g_stats[base_out + 12 + c], q);
        }
    }
}

// one 256-bit load of a 32B fp16 row -> 12 floats (words 6,7 padding)
__device__ __forceinline__ void loadH(float* dst, const __half* hH, int s) {
    const __half* r = hH + ((size_t)s << 4);
    float v0, v1, v2, v3, v4, v5, v6, v7;
    asm volatile("ld.global.nc.v8.f32 {%0,%1,%2,%3,%4,%5,%6,%7}, [%8];"
                 : "=f"(v0), "=f"(v1), "=f"(v2), "=f"(v3),
                   "=f"(v4), "=f"(v5), "=f"(v6), "=f"(v7)
                 : "l"(r));
    unsigned u;
    float2 f;
    u = __float_as_uint(v0); f = __half22float2(*reinterpret_cast<__half2*>(&u)); dst[0] = f.x; dst[1] = f.y;
    u = __float_as_uint(v1); f = __half22float2(*reinterpret_cast<__half2*>(&u)); dst[2] = f.x; dst[3] = f.y;
    u = __float_as_uint(v2); f = __half22float2(*reinterpret_cast<__half2*>(&u)); dst[4] = f.x; dst[5] = f.y;
    u = __float_as_uint(v3); f = __half22float2(*reinterpret_cast<__half2*>(&u)); dst[6] = f.x; dst[7] = f.y;
    u = __float_as_uint(v4); f = __half22float2(*reinterpret_cast<__half2*>(&u)); dst[8] = f.x; dst[9] = f.y;
    u = __float_as_uint(v5); f = __half22float2(*reinterpret_cast<__half2*>(&u)); dst[10] = f.x; dst[11] = f.y;
    (void)v6; (void)v7;
}

__device__ __forceinline__ void gathH(float* acc, const __half* hH, int s) {
    float tmp[12];
    loadH(tmp, hH, s);
#pragma unroll
    for (int j = 0; j < 12; j++) acc[j] += tmp[j];
}

// one 256-bit store of a 32B fp16 row (words 6,7 zero)
__device__ __forceinline__ void storeH(__half* hH, int i, const float* out) {
    __half* r = hH + ((size_t)i << 4);
    unsigned w0, w1, w2, w3, w4, w5;
    *reinterpret_cast<__half2*>(&w0) = __floats2half2_rn(out[0], out[1]);
    *reinterpret_cast<__half2*>(&w1) = __floats2half2_rn(out[2], out[3]);
    *reinterpret_cast<__half2*>(&w2) = __floats2half2_rn(out[4], out[5]);
    *reinterpret_cast<__half2*>(&w3) = __floats2half2_rn(out[6], out[7]);
    *reinterpret_cast<__half2*>(&w4) = __floats2half2_rn(out[8], out[9]);
    *reinterpret_cast<__half2*>(&w5) = __floats2half2_rn(out[10], out[11]);
    asm volatile("st.global.v8.f32 [%0], {%1,%2,%3,%4,%5,%6,%7,%8};"
                 :: "l"(r),
                    "f"(__uint_as_float(w0)), "f"(__uint_as_float(w1)),
                    "f"(__uint_as_float(w2)), "f"(__uint_as_float(w3)),
                    "f"(__uint_as_float(w4)), "f"(__uint_as_float(w5)),
                    "f"(0.f), "f"(0.f)
                 : "memory");
}

// ---------------- CSR build ----------------

__global__ void k_degx(const int* __restrict__ ei, const float* __restrict__ x) {
    int e = blockIdx.x * blockDim.x + threadIdx.x;
    if (e < N_EDGES) atomicAdd(&g_deg[__ldcs(&ei[N_EDGES + e])], 1);
    if (e < N_NODES) {
        g_xp[e] = make_float4(__ldcs(&x[3 * e]), __ldcs(&x[3 * e + 1]),
                              __ldcs(&x[3 * e + 2]), 0.f);
    }
}

__global__ void k_scanA() {
    __shared__ int sh[256];
    int t = threadIdx.x;
    int base = blockIdx.x * 1024 + t * 4;
    int4 d = *reinterpret_cast<int4*>(&g_deg[base]);
    *reinterpret_cast<int4*>(&g_deg[base]) = make_int4(0, 0, 0, 0);
    int s1 = d.x + d.y, s2 = s1 + d.z, tot = s2 + d.w;
    sh[t] = tot;
    __syncthreads();
#pragma unroll
    for (int o = 1; o < 256; o <<= 1) {
        int v = (t >= o) ? sh[t - o] : 0;
        __syncthreads();
        sh[t] += v;
        __syncthreads();
    }
    int excl = sh[t] - tot;
    g_off[base + 0] = excl;
    g_off[base + 1] = excl + d.x;
    g_off[base + 2] = excl + s1;
    g_off[base + 3] = excl + s2;
    if (t == 255) g_bsum[blockIdx.x] = sh[255];
}

__global__ void k_scanB() {
    __shared__ int sred[9];
    int t = threadIdx.x;
    if (blockIdx.x == 0 && t < STATS_LEN) g_stats[t] = 0.f;
    int q = blockIdx.x >> 2;
    int4 v = *reinterpret_cast<int4*>(&g_bsum[t * 4]);
    int j0 = t * 4;
    int s = (j0 + 0 < q ? v.x : 0) + (j0 + 1 < q ? v.y : 0)
          + (j0 + 2 < q ? v.z : 0) + (j0 + 3 < q ? v.w : 0);
#pragma unroll
    for (int o = 16; o; o >>= 1) s += __shfl_xor_sync(0xffffffffu, s, o);
    if ((t & 31) == 0) sred[t >> 5] = s;
    __syncthreads();
    if (t == 0) {
        int r0 = 0;
#pragma unroll
        for (int w = 0; w < 8; w++) r0 += sred[w];
        sred[8] = r0;
    }
    __syncthreads();
    int S = sred[8];
    int i = blockIdx.x * 256 + t;
    int val = g_off[i] + S;
    g_off[i] = val;
    g_cur[i] = val;
    if (i == 0) g_off[N_NODES] = N_EDGES;
}

__global__ void k_place(const int* __restrict__ ei) {
    int e = blockIdx.x * blockDim.x + threadIdx.x;
    if (e >= N_EDGES) return;
    int s = __ldcs(&ei[e]);
    int d = __ldcs(&ei[N_EDGES + e]);
    int p = atomicAdd(&g_cur[d], 1);
    g_srt[p] = s;
}

// ---------------- layer 1: float4-packed x gather; output fp16 mirror only -------
__global__ void k_node1f(const float* __restrict__ Wl1, const float* __restrict__ Wr1,
                         const float* __restrict__ b1) {
    __shared__ float sWl[36], sWr[36], sb[12];
    __shared__ float sOut[256 * 13];
    int t = threadIdx.x;
    if (t < 36) { sWl[t] = Wl1[t]; sWr[t] = Wr1[t]; }
    if (t < 12) sb[t] = b1[t];
    __syncthreads();
    int i = blockIdx.x * blockDim.x + t;
    int beg = g_off[i], end = g_off[i + 1];
    float a0 = 0.f, a1 = 0.f, a2 = 0.f;
    int p = beg;
    for (; p + 2 <= end; p += 2) {
        int s0 = __ldg(&g_srt[p]), s1 = __ldg(&g_srt[p + 1]);
        float4 u = __ldg(&g_xp[s0]);
        float4 w = __ldg(&g_xp[s1]);
        a0 += u.x + w.x; a1 += u.y + w.y; a2 += u.z + w.z;
    }
    if (p < end) {
        float4 u = __ldg(&g_xp[__ldg(&g_srt[p])]);
        a0 += u.x; a1 += u.y; a2 += u.z;
    }
    int dg = end - beg;
    float inv = dg > 0 ? 1.f / (float)dg : 0.f;
    float m0 = a0 * inv, m1 = a1 * inv, m2 = a2 * inv;
    float4 xs = __ldg(&g_xp[i]);
    float out[12];
#pragma unroll
    for (int k = 0; k < 12; k++) {
        float v = sb[k] + m0 * sWl[3 * k] + m1 * sWl[3 * k + 1] + m2 * sWl[3 * k + 2]
                        + xs.x * sWr[3 * k] + xs.y * sWr[3 * k + 1] + xs.z * sWr[3 * k + 2];
        out[k] = fmaxf(v, 0.f);
    }
    storeH(g_hHA, i, out);
#pragma unroll
    for (int k = 0; k < 12; k++) sOut[t * 13 + k] = out[k];
    stats_reduce<true>(sOut, t, 0);
}

// ---------------- layers 2..8: all-fp16 state, f32x2 GEMV ----------------
// Weights staged in shared as output-channel PAIRS: sWl2[j*6+kp] = {Wl[2kp][j], Wl[2kp+1][j]}.
// GEMV over pairs with fma.rn.f32x2 (exact fp32, 2 MACs/instr, LDS.64 per weight pair).
// MODE 0 (conv2..7): output fp16 mirror only, conv stats.
// MODE 1 (conv8):    output fp32 h_out (head chain needs fp32), head z1 stats.
template <int MODE>
__global__ void k_nodef(int in_sel, int out_sel,
                        const float* __restrict__ Wl, const float* __restrict__ Wr,
                        const float* __restrict__ bias,
                        const float* __restrict__ bng, const float* __restrict__ bnb,
                        int sin_off, int sout_off,
                        const float* __restrict__ linW, const float* __restrict__ linb) {
    const __half* hH_in = bufptrH(in_sel);
    float*  h_out  = bufptr(out_sel);
    __half* hH_out = bufptrH(out_sel);
    __shared__ float2 sWl2[72], sWr2[72];
    __shared__ float sb[12], sa[12], sc[12], sLW[36], sLB[6];
    __shared__ float sOut[256 * 13];
    int t = threadIdx.x;
    if (t < 72) {
        int j = t / 6, kp = t % 6;
        sWl2[t] = make_float2(Wl[(2 * kp) * 12 + j], Wl[(2 * kp + 1) * 12 + j]);
        sWr2[t] = make_float2(Wr[(2 * kp) * 12 + j], Wr[(2 * kp + 1) * 12 + j]);
    }
    if (t < 12) {
        sb[t] = bias[t];
        float mean = g_stats[sin_off + t] * (1.f / N_NODES);
        float var  = g_stats[sin_off + 12 + t] * (1.f / N_NODES) - mean * mean;
        float a = bng[t] * rsqrtf(var + EPSV);
        sa[t] = a;
        sc[t] = bnb[t] - mean * a;
    }
    if (MODE == 1) {
        if (t < 36) sLW[t] = linW[t];
        if (t < 6)  sLB[t] = linb[t];
    }
    __syncthreads();
    int i = blockIdx.x * blockDim.x + t;
    int beg = g_off[i], end = g_off[i + 1];
    float acc[12];
#pragma unroll
    for (int j = 0; j < 12; j++) acc[j] = 0.f;
    int p = beg;
    for (; p + 2 <= end; p += 2) {
        int s0 = __ldg(&g_srt[p]), s1 = __ldg(&g_srt[p + 1]);
        gathH(acc, hH_in, s0);
        gathH(acc, hH_in, s1);
    }
    if (p < end) gathH(acc, hH_in, __ldg(&g_srt[p]));

    float hv[12];
    loadH(hv, hH_in, i);            // self row from fp16 mirror (1 wavefront)
    int dg = end - beg;
    float gate = dg > 0 ? 1.f : 0.f;
    float inv  = dg > 0 ? 1.f / (float)dg : 0.f;
    float m[12], hb[12];
#pragma unroll
    for (int j = 0; j < 12; j++) {
        m[j]  = acc[j] * inv * sa[j] + sc[j] * gate;   // bn(mean) fold; isolated -> 0
        hb[j] = hv[j] * sa[j] + sc[j];
    }
    // f32x2 GEMV over 6 output-channel pairs (same per-channel FP order as scalar)
    const unsigned long long* wl2 = reinterpret_cast<const unsigned long long*>(sWl2);
    const unsigned long long* wr2 = reinterpret_cast<const unsigned long long*>(sWr2);
    unsigned long long acc2[6];
#pragma unroll
    for (int kp = 0; kp < 6; kp++) acc2[kp] = pack2(sb[2 * kp], sb[2 * kp + 1]);
#pragma unroll
    for (int j = 0; j < 12; j++) {
        unsigned long long mj = pack2(m[j], m[j]);
        unsigned long long hj = pack2(hb[j], hb[j]);
#pragma unroll
        for (int kp = 0; kp < 6; kp++) {
            fma2(acc2[kp], mj, wl2[j * 6 + kp]);
            fma2(acc2[kp], hj, wr2[j * 6 + kp]);
        }
    }
    float out[12];
#pragma unroll
    for (int kp = 0; kp < 6; kp++) {
        float u, v;
        unpack2(acc2[kp], u, v);
        out[2 * kp]     = fmaxf(u, 0.f);
        out[2 * kp + 1] = fmaxf(v, 0.f);
    }
    if (MODE == 0) {
        storeH(hH_out, i, out);
#pragma unroll
        for (int k = 0; k < 12; k++) sOut[t * 13 + k] = out[k];
        stats_reduce<true>(sOut, t, sout_off);
    } else {
        float4* op = reinterpret_cast<float4*>(h_out + (size_t)i * 12);
        __stcs(op + 0, make_float4(out[0], out[1], out[2], out[3]));
        __stcs(op + 1, make_float4(out[4], out[5], out[6], out[7]));
        __stcs(op + 2, make_float4(out[8], out[9], out[10], out[11]));
#pragma unroll
        for (int k = 0; k < 6; k++) {
            float za = sLB[k], zb = sLB[k];
#pragma unroll
            for (int j = 0; j < 6; j++) { za += out[j] * sLW[6 * k + j]; zb += out[6 + j] * sLW[6 * k + j]; }
            sOut[t * 13 + k]     = za + zb;
            sOut[t * 13 + 6 + k] = za * za + zb * zb;
        }
        stats_reduce<false>(sOut, t, sout_off);
    }
}

// ---------------- head (all fp32, streaming) ----------------
template <int PASS>
__global__ void k_head(int in_sel, int out_sel,
                       const float* __restrict__ linW, const float* __restrict__ linb,
                       const float* __restrict__ g6, const float* __restrict__ b6,
                       int sin_off, int sout_off,
                       const float* __restrict__ oW, const float* __restrict__ ob,
                       float* __restrict__ outp) {
    const float* h_in = bufptr(in_sel);
    float* h_out = bufptr(out_sel);
    __shared__ float sLW[36], sLB[6], sa[6], sc[6], sOW[7];
    __shared__ float sOut[256 * 13];
    int t = threadIdx.x;
    if (t < 36) sLW[t] = linW[t];
    if (t < 6) {
        sLB[t] = linb[t];
        const float invM = 1.f / (2.f * N_NODES);
        float mean = g_stats[sin_off + t] * invM;
        float var  = g_stats[sin_off + 6 + t] * invM - mean * mean;
        float a = g6[t] * rsqrtf(var + EPSV);
        sa[t] = a;
        sc[t] = b6[t] - mean * a;
    }
    if (PASS == 3) { if (t < 6) sOW[t] = oW[t]; if (t == 6) sOW[6] = ob[0]; }
    __syncthreads();
    int i = blockIdx.x * blockDim.x + t;
    const float4* hp = reinterpret_cast<const float4*>(h_in + (size_t)i * 12);
    float4 h0 = __ldcs(hp + 0), h1 = __ldcs(hp + 1), h2 = __ldcs(hp + 2);
    float hv[12] = {h0.x, h0.y, h0.z, h0.w, h1.x, h1.y, h1.z, h1.w, h2.x, h2.y, h2.z, h2.w};
    float r[12];
#pragma unroll
    for (int half = 0; half < 2; half++) {
#pragma unroll
        for (int k = 0; k < 6; k++) {
            float z = sLB[k];
#pragma unroll
            for (int j = 0; j < 6; j++) z += hv[6 * half + j] * sLW[6 * k + j];
            r[6 * half + k] = fmaxf(z * sa[k] + sc[k], 0.f);
        }
    }
    if (PASS < 3) {
        float4* op = reinterpret_cast<float4*>(h_out + (size_t)i * 12);
        __stcs(op + 0, make_float4(r[0], r[1], r[2], r[3]));
        __stcs(op + 1, make_float4(r[4], r[5], r[6], r[7]));
        __stcs(op + 2, make_float4(r[8], r[9], r[10], r[11]));
#pragma unroll
        for (int k = 0; k < 6; k++) {
            float za = sLB[k], zb = sLB[k];
#pragma unroll
            for (int j = 0; j < 6; j++) { za += r[j] * sLW[6 * k + j]; zb += r[6 + j] * sLW[6 * k + j]; }
            sOut[t * 13 + k]     = za + zb;
            sOut[t * 13 + 6 + k] = za * za + zb * zb;
        }
        stats_reduce<false>(sOut, t, sout_off);
    } else {
        float oa = sOW[6], obv = sOW[6];
#pragma unroll
        for (int j = 0; j < 6; j++) { oa += r[j] * sOW[j]; obv += r[6 + j] * sOW[j]; }
        outp[2 * i]     = 1.f / (1.f + expf(-oa));
        outp[2 * i + 1] = 1.f / (1.f + expf(-obv));
    }
}

// ---------------- launch ----------------
extern "C" void kernel_launch(void* const* d_in, const int* in_sizes, int n_in,
                              void* d_out, int out_size) {
    const float* x    = (const float*)d_in[0];
    const int*   ei   = (const int*)d_in[1];
    const float* Wl1  = (const float*)d_in[2];
    const float* Wr1  = (const float*)d_in[3];
    const float* b1   = (const float*)d_in[4];
    const float* Wl   = (const float*)d_in[5];
    const float* Wr   = (const float*)d_in[6];
    const float* bb   = (const float*)d_in[7];
    const float* bng  = (const float*)d_in[8];
    const float* bnb  = (const float*)d_in[9];
    const float* linW = (const float*)d_in[10];
    const float* linb = (const float*)d_in[11];
    const float* g6   = (const float*)d_in[12];
    const float* b6   = (const float*)d_in[13];
    const float* oW   = (const float*)d_in[14];
    const float* ob   = (const float*)d_in[15];
    float* outp = (float*)d_out;

    const int EB = N_EDGES / 256;   // 16384
    const int NB = N_NODES / 256;   // 4096

    // CSR build (g_deg/g_stats zero at entry: load-time init or fused re-zeroing)
    k_degx<<<EB, 256>>>(ei, x);
    k_scanA<<<1024, 256>>>();       // also re-zeroes g_deg for next call
    k_scanB<<<NB, 256>>>();         // block 0 also re-zeroes g_stats
    k_place<<<EB, 256>>>(ei);

    // conv1 -> hHA (fp16), stats slot 0
    k_node1f<<<NB, 256>>>(Wl1, Wr1, b1);

    int in_sel = 0, out_sel = 1;
    for (int i = 0; i < 7; i++) {
        int sin_off = 24 * i;
        if (i < 6) {
            k_nodef<0><<<NB, 256>>>(in_sel, out_sel, Wl + 144 * i, Wr + 144 * i, bb + 12 * i,
                                    bng + 12 * i, bnb + 12 * i, sin_off, 24 * (i + 1),
                                    linW, linb);
        } else {
            k_nodef<1><<<NB, 256>>>(in_sel, out_sel, Wl + 144 * i, Wr + 144 * i, bb + 12 * i,
                                    bng + 12 * i, bnb + 12 * i, sin_off, 7 * 24,
                                    linW, linb);
        }
        int tmp = in_sel; in_sel = out_sel; out_sel = tmp;
    }
    // conv8 output (fp32) in g_hB. Head: hB -> hA -> hB -> out.
    k_head<1><<<NB, 256>>>(1, 0, linW, linb, g6, b6, 168, 180, oW, ob, outp);
    k_head<2><<<NB, 256>>>(0, 1, linW, linb, g6, b6, 180, 192, oW, ob, outp);
    k_head<3><<<NB, 256>>>(1, 0, linW, linb, g6, b6, 192, 0, oW, ob, outp);
}